// round 14
// baseline (speedup 1.0000x reference)
#include <cuda_runtime.h>
#include <cuda_fp16.h>
#include <math.h>
#include <stdint.h>

// Problem constants (fixed dataset)
#define NATOMS_MAX 10000
#define NEDGE_MAX  320000
#define HD 128      // hidden = filter dim
#define HD4 (HD/4)
#define GD 50       // gaussians
#define LD 6        // layers

#define NGRID 2048
#define WMAX  6.0f
#define HSTEP (WMAX / (float)(NGRID - 1))
#define INVH  ((float)(NGRID - 1) / WMAX)

#define DELTA   (4.0f/49.0f)
#define COEF    (-0.5f/(DELTA*DELTA))
#define TWOC    (2.0f*COEF)
#define PI_F    3.14159265358979323846f
#define LN2_F   0.6931471805599453f

// ---------------- scratch (static device globals; no allocation) ----------------
__device__ float g_vec[(size_t)NEDGE_MAX*3];
__device__ float g_w[NEDGE_MAX];
__device__ float4 g_epk[NEDGE_MAX];   // packed per-edge: {t, C, dC, bitcast(r)}
__device__ float g_gradw[NEDGE_MAX];

// filter tables: fp32 staging (GEMM out) + fp16 final
__device__ float g_Wt32 [(size_t)LD*NGRID*HD];
__device__ float g_Wpt32[(size_t)LD*NGRID*HD];
__device__ __half g_Wth [(size_t)LD*NGRID*HD];
__device__ __half g_Wpth[(size_t)LD*NGRID*HD];
__device__ float g_eag  [(size_t)NGRID*GD];
__device__ float g_deag [(size_t)NGRID*GD];
__device__ float g_t1g  [(size_t)LD*NGRID*HD];
__device__ float g_dt1g [(size_t)LD*NGRID*HD];

__device__ float  g_h  [(size_t)(LD+1)*NATOMS_MAX*HD];
__device__ float4 g_xh4[(size_t)LD*NATOMS_MAX*HD4];
__device__ float  g_m  [(size_t)LD*NATOMS_MAX*HD];
__device__ float4 g_agg4[(size_t)NATOMS_MAX*HD4];
__device__ float  g_gh [(size_t)NATOMS_MAX*HD];
__device__ float4 g_gxh4[(size_t)NATOMS_MAX*HD4];

// ---------------- math helpers ----------------
__device__ __forceinline__ float sspf(float x) {
    return fmaxf(x, 0.0f) + log1pf(expf(-fabsf(x))) - LN2_F;
}
__device__ __forceinline__ float sigf(float x) {
    return 1.0f / (1.0f + expf(-x));
}
__device__ __forceinline__ void red_add_v4(float* p, float4 v) {
    asm volatile("red.global.add.v4.f32 [%0], {%1,%2,%3,%4};"
                 :: "l"(p), "f"(v.x), "f"(v.y), "f"(v.z), "f"(v.w) : "memory");
}
// lerp a 128-ch fp16 table row pair at (i0, f); lane handles 4 channels
__device__ __forceinline__ float4 lerp_row_h(const __half* __restrict__ tab,
                                             int i0, float f, int lane) {
    const char* base = (const char*)(tab + (size_t)i0 * HD + lane * 4);
    uint2 ua = *(const uint2*)base;
    uint2 ub = *(const uint2*)(base + HD * 2);
    float2 a0 = __half22float2(*(__half2*)&ua.x);
    float2 a1 = __half22float2(*(__half2*)&ua.y);
    float2 b0 = __half22float2(*(__half2*)&ub.x);
    float2 b1 = __half22float2(*(__half2*)&ub.y);
    float4 o;
    o.x = fmaf(f, b0.x - a0.x, a0.x);
    o.y = fmaf(f, b0.y - a0.y, a0.y);
    o.z = fmaf(f, b1.x - a1.x, a1.x);
    o.w = fmaf(f, b1.y - a1.y, a1.y);
    return o;
}

// ---------------- edge geometry (+ packed params) ----------------
__global__ void k_edge_geom(const float* __restrict__ pos, const int* __restrict__ ei,
                            const float* __restrict__ off, const float* __restrict__ cell, int E) {
    int e = blockIdx.x * blockDim.x + threadIdx.x;
    if (e >= E) return;
    int r = ei[e], c = ei[E + e];
    float o0 = off[e*3+0], o1 = off[e*3+1], o2 = off[e*3+2];
    float v0 = pos[r*3+0] - pos[c*3+0] + o0*cell[0] + o1*cell[3] + o2*cell[6];
    float v1 = pos[r*3+1] - pos[c*3+1] + o0*cell[1] + o1*cell[4] + o2*cell[7];
    float v2 = pos[r*3+2] - pos[c*3+2] + o0*cell[2] + o1*cell[5] + o2*cell[8];
    float w = sqrtf(v0*v0 + v1*v1 + v2*v2);
    g_vec[(size_t)e*3+0] = v0; g_vec[(size_t)e*3+1] = v1; g_vec[(size_t)e*3+2] = v2;
    g_w[e] = w;
    float a = w * (PI_F / 4.0f);
    float C  = 0.5f * (cosf(a) + 1.0f);
    float dC = -0.5f * sinf(a) * (PI_F / 4.0f);
    float t  = fminf(w, WMAX) * INVH;
    g_epk[e] = make_float4(t, C, dC, __int_as_float(r));
}

// ---------------- gaussian grid (once) ----------------
__global__ void k_tab_ea() {
    int idx = blockIdx.x * blockDim.x + threadIdx.x;
    if (idx >= NGRID * GD) return;
    int g = idx / GD, j = idx % GD;
    float w = (float)g * HSTEP;
    float d = w - (float)j * DELTA;
    float ea = expf(COEF * d * d);
    g_eag[idx]  = ea;
    g_deag[idx] = TWOC * d * ea;
}

__global__ void k_h0(const int* __restrict__ z, const float* __restrict__ emb,
                     float* __restrict__ h, int N) {
    int idx = blockIdx.x * blockDim.x + threadIdx.x;
    if (idx >= N * HD) return;
    int n = idx >> 7, k = idx & 127;
    h[idx] = emb[(size_t)z[n] * HD + k];
}

__global__ void k_cvt_h(const float* __restrict__ a, const float* __restrict__ b,
                        __half* __restrict__ ha, __half* __restrict__ hb, size_t n) {
    size_t i = (size_t)blockIdx.x * blockDim.x + threadIdx.x;
    if (i >= n) return;
    ha[i] = __float2half_rn(a[i]);
    hb[i] = __float2half_rn(b[i]);
}

// ---------------- tiled fp32 GEMM (tables + xh0) ----------------
template<bool TB, int AOP, int EPI>
__global__ __launch_bounds__(256)
void k_gemm(const float* __restrict__ A, const float* __restrict__ B,
            const float* __restrict__ bias, const float* __restrict__ add_,
            const float* __restrict__ aux, float* __restrict__ Co,
            int M, int Nn, int K,
            size_t sA, size_t sB, size_t sBias, size_t sC) {
    const int BM = 64, BN = 64, BK = 16;
    int zb = blockIdx.z;
    A  += (size_t)zb * sA;
    B  += (size_t)zb * sB;
    Co += (size_t)zb * sC;
    const float* bi = bias ? bias + (size_t)zb * sBias : nullptr;
    const float* ax2 = (AOP == 2) ? add_ + (size_t)zb * sA : nullptr;

    __shared__ float As[BK][BM + 4];
    __shared__ float Bs[BK][BN + 4];
    int bm = blockIdx.y * BM, bn = blockIdx.x * BN;
    int tid = threadIdx.x;
    int tx = tid & 15, ty = tid >> 4;
    int la_k = tid & 15, la_r = tid >> 4;
    float acc[4][4];
#pragma unroll
    for (int i = 0; i < 4; i++)
#pragma unroll
        for (int j = 0; j < 4; j++) acc[i][j] = 0.0f;

    for (int k0 = 0; k0 < K; k0 += BK) {
#pragma unroll
        for (int i = 0; i < 4; i++) {
            int m = bm + la_r + i * 16;
            int k = k0 + la_k;
            float v = 0.0f;
            if (m < M && k < K) {
                v = A[(size_t)m * K + k];
                if (AOP == 1) v = sspf(v);
                if (AOP == 2) v *= sigf(ax2[(size_t)m * K + k]);
            }
            As[la_k][la_r + i * 16] = v;
        }
#pragma unroll
        for (int i = 0; i < 4; i++) {
            int idx = tid + i * 256;
            int kk = idx >> 6;
            int nn = idx & 63;
            int k = k0 + kk, n = bn + nn;
            float v = 0.0f;
            if (k < K && n < Nn) v = TB ? B[(size_t)n * K + k] : B[(size_t)k * Nn + n];
            Bs[kk][nn] = v;
        }
        __syncthreads();
#pragma unroll
        for (int k = 0; k < BK; k++) {
            float ra[4], rb[4];
#pragma unroll
            for (int i = 0; i < 4; i++) ra[i] = As[k][ty * 4 + i];
#pragma unroll
            for (int j = 0; j < 4; j++) rb[j] = Bs[k][tx * 4 + j];
#pragma unroll
            for (int i = 0; i < 4; i++)
#pragma unroll
                for (int j = 0; j < 4; j++) acc[i][j] = fmaf(ra[i], rb[j], acc[i][j]);
        }
        __syncthreads();
    }
#pragma unroll
    for (int i = 0; i < 4; i++) {
        int m = bm + ty * 4 + i;
        if (m >= M) continue;
#pragma unroll
        for (int j = 0; j < 4; j++) {
            int n = bn + tx * 4 + j;
            if (n >= Nn) continue;
            float v = acc[i][j];
            if (bi) v += bi[n];
            size_t o = (size_t)m * Nn + n;
            if (EPI == 1) v += add_[o];
            if (EPI == 2) v *= sigf(aux[o]);
            Co[o] = v;
        }
    }
}

// ============ fused multi-stage node kernels (32-row blocks, 256 thr, 2 CTA/SM) ============
__device__ __forceinline__ void load_B_nt(const float* __restrict__ B, float Bs[16][132],
                                          int k0, int tid) {
#pragma unroll
    for (int i = 0; i < 8; i++) {
        int idx = tid + i * 256;
        int kk = idx >> 7, nn = idx & 127;
        Bs[kk][nn] = B[(size_t)(k0 + kk) * HD + nn];
    }
}
__device__ __forceinline__ void load_B_t(const float* __restrict__ B, float Bs[16][132],
                                         int k0, int tid) {
#pragma unroll
    for (int i = 0; i < 8; i++) {
        int idx = tid + i * 256;
        int kk = idx & 15, nn = idx >> 4;
        Bs[kk][nn] = B[(size_t)nn * HD + (k0 + kk)];
    }
}
__device__ __forceinline__ void load_A_g32(const float* __restrict__ A, float As[16][36],
                                           int bm, int k0, int tid, int N) {
#pragma unroll
    for (int i = 0; i < 2; i++) {
        int idx = tid + i * 256;
        int kk = idx & 15, rr = idx >> 4;
        int gm = bm + rr;
        As[kk][rr] = (gm < N) ? A[(size_t)gm * HD + k0 + kk] : 0.0f;
    }
}
__device__ __forceinline__ void fma_as32(const float As[16][36], const float Bs[16][132],
                                         float acc[2][8], int tx, int ty) {
#pragma unroll
    for (int k = 0; k < 16; k++) {
        float ra[2];
#pragma unroll
        for (int i = 0; i < 2; i++) ra[i] = As[k][ty * 2 + i];
        float4 b0 = *(const float4*)&Bs[k][tx * 8];
        float4 b1 = *(const float4*)&Bs[k][tx * 8 + 4];
        float rb[8] = {b0.x, b0.y, b0.z, b0.w, b1.x, b1.y, b1.z, b1.w};
#pragma unroll
        for (int i = 0; i < 2; i++)
#pragma unroll
            for (int j = 0; j < 8; j++) acc[i][j] = fmaf(ra[i], rb[j], acc[i][j]);
    }
}
__device__ __forceinline__ void fma_ms32(const float Ms[32][132], const float Bs[16][132],
                                         float acc[2][8], int k0, int tx, int ty) {
#pragma unroll
    for (int k = 0; k < 16; k++) {
        float ra[2];
#pragma unroll
        for (int i = 0; i < 2; i++) ra[i] = Ms[ty * 2 + i][k0 + k];
        float4 b0 = *(const float4*)&Bs[k][tx * 8];
        float4 b1 = *(const float4*)&Bs[k][tx * 8 + 4];
        float rb[8] = {b0.x, b0.y, b0.z, b0.w, b1.x, b1.y, b1.z, b1.w};
#pragma unroll
        for (int i = 0; i < 2; i++)
#pragma unroll
            for (int j = 0; j < 8; j++) acc[i][j] = fmaf(ra[i], rb[j], acc[i][j]);
    }
}
__device__ __forceinline__ void zero_acc2(float acc[2][8]) {
#pragma unroll
    for (int i = 0; i < 2; i++)
#pragma unroll
        for (int j = 0; j < 8; j++) acc[i][j] = 0.0f;
}

// fused forward per layer: m = agg@w2+b2 ; hn = hi + ssp(m)@lw+lb ; xhn = hn@cw1n (optional)
// ALSO re-zeros agg rows (ready for the next layer's scatter) after consuming them.
__global__ __launch_bounds__(256)
void k_fused_fwd(float* __restrict__ agg, const float* __restrict__ w2,
                 const float* __restrict__ b2, const float* __restrict__ lw,
                 const float* __restrict__ lb, const float* __restrict__ hi,
                 const float* __restrict__ cw1n,
                 float* __restrict__ m_out, float* __restrict__ hn,
                 float* __restrict__ xhn, int N) {
    __shared__ float As[16][36];
    __shared__ float Bs[16][132];
    __shared__ float Ms[32][132];
    int bm = blockIdx.x * 32;
    int tid = threadIdx.x, tx = tid & 15, ty = tid >> 4;
    float acc[2][8];
    zero_acc2(acc);

    // stage 1: m = agg @ w2
    for (int k0 = 0; k0 < HD; k0 += 16) {
        load_A_g32(agg, As, bm, k0, tid, N);
        load_B_nt(w2, Bs, k0, tid);
        __syncthreads();
        fma_as32(As, Bs, acc, tx, ty);
        __syncthreads();
    }
    const float4 z4 = make_float4(0.f, 0.f, 0.f, 0.f);
#pragma unroll
    for (int i = 0; i < 2; i++) {
        int row = ty * 2 + i;
        int gm = bm + row;
        float4 v0, v1;
        float* vv0 = (float*)&v0; float* vv1 = (float*)&v1;
#pragma unroll
        for (int j = 0; j < 8; j++) {
            int c = tx * 8 + j;
            float v = acc[i][j] + b2[c];
            Ms[row][c] = sspf(v);
            if (j < 4) vv0[j] = v; else vv1[j - 4] = v;
            acc[i][j] = 0.0f;
        }
        if (gm < N) {
            *(float4*)&m_out[(size_t)gm * HD + tx * 8]     = v0;
            *(float4*)&m_out[(size_t)gm * HD + tx * 8 + 4] = v1;
            // re-zero agg for next layer's scatter
            *(float4*)&agg[(size_t)gm * HD + tx * 8]     = z4;
            *(float4*)&agg[(size_t)gm * HD + tx * 8 + 4] = z4;
        }
    }
    __syncthreads();

    // stage 2: hn = Ms(ssp(m)) @ lw + lb + hi
    for (int k0 = 0; k0 < HD; k0 += 16) {
        load_B_nt(lw, Bs, k0, tid);
        __syncthreads();
        fma_ms32(Ms, Bs, acc, k0, tx, ty);
        __syncthreads();
    }
#pragma unroll
    for (int i = 0; i < 2; i++) {
        int row = ty * 2 + i;
        int gm = bm + row;
        float hiv[8];
        if (gm < N) {
            float4 a = *(const float4*)&hi[(size_t)gm * HD + tx * 8];
            float4 b = *(const float4*)&hi[(size_t)gm * HD + tx * 8 + 4];
            hiv[0]=a.x; hiv[1]=a.y; hiv[2]=a.z; hiv[3]=a.w;
            hiv[4]=b.x; hiv[5]=b.y; hiv[6]=b.z; hiv[7]=b.w;
        } else {
#pragma unroll
            for (int j = 0; j < 8; j++) hiv[j] = 0.0f;
        }
        float4 v0, v1;
        float* vv0 = (float*)&v0; float* vv1 = (float*)&v1;
#pragma unroll
        for (int j = 0; j < 8; j++) {
            int c = tx * 8 + j;
            float v = acc[i][j] + lb[c] + hiv[j];
            Ms[row][c] = v;    // safe: all stage-2 reads done (last sync)
            if (j < 4) vv0[j] = v; else vv1[j - 4] = v;
            acc[i][j] = 0.0f;
        }
        if (gm < N) {
            *(float4*)&hn[(size_t)gm * HD + tx * 8]     = v0;
            *(float4*)&hn[(size_t)gm * HD + tx * 8 + 4] = v1;
        }
    }
    if (!cw1n) return;
    __syncthreads();

    // stage 3: xhn = Ms(hn) @ cw1n
    for (int k0 = 0; k0 < HD; k0 += 16) {
        load_B_nt(cw1n, Bs, k0, tid);
        __syncthreads();
        fma_ms32(Ms, Bs, acc, k0, tx, ty);
        __syncthreads();
    }
#pragma unroll
    for (int i = 0; i < 2; i++) {
        int gm = bm + ty * 2 + i;
        if (gm >= N) continue;
        float4 v0, v1;
        v0.x=acc[i][0]; v0.y=acc[i][1]; v0.z=acc[i][2]; v0.w=acc[i][3];
        v1.x=acc[i][4]; v1.y=acc[i][5]; v1.z=acc[i][6]; v1.w=acc[i][7];
        *(float4*)&xhn[(size_t)gm * HD + tx * 8]     = v0;
        *(float4*)&xhn[(size_t)gm * HD + tx * 8 + 4] = v1;
    }
}

// fused backward per layer j; ALSO re-zeros gxh rows for the following scatter_bwd.
__global__ __launch_bounds__(256)
void k_fused_bwd(float* __restrict__ gh, float* __restrict__ gxh, int has_gxh,
                 const float* __restrict__ cw1n, const float* __restrict__ lw,
                 const float* __restrict__ m, const float* __restrict__ w2,
                 float* __restrict__ gagg, int N) {
    __shared__ float As[16][36];
    __shared__ float Bs[16][132];
    __shared__ float Ms[32][132];
    int bm = blockIdx.x * 32;
    int tid = threadIdx.x, tx = tid & 15, ty = tid >> 4;
    float acc[2][8];
    zero_acc2(acc);

    // stage 0: gh += gxh @ cw1n^T
    if (has_gxh) {
        for (int k0 = 0; k0 < HD; k0 += 16) {
            load_A_g32(gxh, As, bm, k0, tid, N);
            load_B_t(cw1n, Bs, k0, tid);
            __syncthreads();
            fma_as32(As, Bs, acc, tx, ty);
            __syncthreads();
        }
    }
    const float4 z4 = make_float4(0.f, 0.f, 0.f, 0.f);
#pragma unroll
    for (int i = 0; i < 2; i++) {
        int row = ty * 2 + i;
        int gm = bm + row;
        float ghv[8];
        if (gm < N) {
            float4 a = *(const float4*)&gh[(size_t)gm * HD + tx * 8];
            float4 b = *(const float4*)&gh[(size_t)gm * HD + tx * 8 + 4];
            ghv[0]=a.x; ghv[1]=a.y; ghv[2]=a.z; ghv[3]=a.w;
            ghv[4]=b.x; ghv[5]=b.y; ghv[6]=b.z; ghv[7]=b.w;
        } else {
#pragma unroll
            for (int j = 0; j < 8; j++) ghv[j] = 0.0f;
        }
        float4 v0, v1;
        float* vv0 = (float*)&v0; float* vv1 = (float*)&v1;
#pragma unroll
        for (int j = 0; j < 8; j++) {
            int c = tx * 8 + j;
            float v = acc[i][j] + ghv[j];
            Ms[row][c] = v;
            if (j < 4) vv0[j] = v; else vv1[j - 4] = v;
            acc[i][j] = 0.0f;
        }
        if (gm < N) {
            if (has_gxh) {
                *(float4*)&gh[(size_t)gm * HD + tx * 8]     = v0;
                *(float4*)&gh[(size_t)gm * HD + tx * 8 + 4] = v1;
            }
            // re-zero gxh for this layer's scatter_bwd accumulation
            *(float4*)&gxh[(size_t)gm * HD + tx * 8]     = z4;
            *(float4*)&gxh[(size_t)gm * HD + tx * 8 + 4] = z4;
        }
    }
    __syncthreads();

    // stage 1: t = Ms(gh) @ lw^T, then gate by sigmoid(m)
    for (int k0 = 0; k0 < HD; k0 += 16) {
        load_B_t(lw, Bs, k0, tid);
        __syncthreads();
        fma_ms32(Ms, Bs, acc, k0, tx, ty);
        __syncthreads();
    }
#pragma unroll
    for (int i = 0; i < 2; i++) {
        int row = ty * 2 + i;
        int gm = bm + row;
        float mv[8];
        if (gm < N) {
            float4 a = *(const float4*)&m[(size_t)gm * HD + tx * 8];
            float4 b = *(const float4*)&m[(size_t)gm * HD + tx * 8 + 4];
            mv[0]=a.x; mv[1]=a.y; mv[2]=a.z; mv[3]=a.w;
            mv[4]=b.x; mv[5]=b.y; mv[6]=b.z; mv[7]=b.w;
        } else {
#pragma unroll
            for (int j = 0; j < 8; j++) mv[j] = 0.0f;
        }
#pragma unroll
        for (int j = 0; j < 8; j++) {
            int c = tx * 8 + j;
            Ms[row][c] = acc[i][j] * sigf(mv[j]);
            acc[i][j] = 0.0f;
        }
    }
    __syncthreads();

    // stage 2: gagg = Ms(gn) @ w2^T (full overwrite)
    for (int k0 = 0; k0 < HD; k0 += 16) {
        load_B_t(w2, Bs, k0, tid);
        __syncthreads();
        fma_ms32(Ms, Bs, acc, k0, tx, ty);
        __syncthreads();
    }
#pragma unroll
    for (int i = 0; i < 2; i++) {
        int gm = bm + ty * 2 + i;
        if (gm >= N) continue;
        float4 v0, v1;
        v0.x=acc[i][0]; v0.y=acc[i][1]; v0.z=acc[i][2]; v0.w=acc[i][3];
        v1.x=acc[i][4]; v1.y=acc[i][5]; v1.z=acc[i][6]; v1.w=acc[i][7];
        *(float4*)&gagg[(size_t)gm * HD + tx * 8]     = v0;
        *(float4*)&gagg[(size_t)gm * HD + tx * 8 + 4] = v1;
    }
}

// ---------------- scatter forward: warp per edge, fp16 table lerp, red.v4 ----------------
__global__ __launch_bounds__(256)
void k_scatter_fwd(const float4* __restrict__ xh, const __half* __restrict__ Wth,
                   const int* __restrict__ ei, float4* __restrict__ agg, int E) {
    int e = (int)(((size_t)blockIdx.x * blockDim.x + threadIdx.x) >> 5);
    int lane = threadIdx.x & 31;
    if (e >= E) return;
    float4 pk = g_epk[e];
    float t = pk.x, cc = pk.y;
    int r = __float_as_int(pk.w);
    int c = ei[E + e];
    int i0 = min((int)t, NGRID - 2);
    float f = t - (float)i0;
    float4 W = lerp_row_h(Wth, i0, f, lane);
    float4 x = xh[(size_t)r * HD4 + lane];
    float4 v;
    v.x = W.x * cc * x.x;
    v.y = W.y * cc * x.y;
    v.z = W.z * cc * x.z;
    v.w = W.w * cc * x.w;
    red_add_v4((float*)(agg + (size_t)c * HD4 + lane), v);
}

// ---------------- scatter backward: warp per edge ----------------
__global__ __launch_bounds__(256)
void k_scatter_bwd(const float4* __restrict__ xh, const __half* __restrict__ Wth,
                   const __half* __restrict__ Wpth,
                   const float4* __restrict__ gagg, const int* __restrict__ ei,
                   float4* __restrict__ gxh, int E) {
    int e = (int)(((size_t)blockIdx.x * blockDim.x + threadIdx.x) >> 5);
    int lane = threadIdx.x & 31;
    if (e >= E) return;
    float4 pk = g_epk[e];
    float t = pk.x, cc = pk.y, dc = pk.z;
    int r = __float_as_int(pk.w);
    int c = ei[E + e];
    int i0 = min((int)t, NGRID - 2);
    float f = t - (float)i0;
    float4 W  = lerp_row_h(Wth,  i0, f, lane);
    float4 Wp = lerp_row_h(Wpth, i0, f, lane);
    float4 x = xh[(size_t)r * HD4 + lane];
    float4 g = gagg[(size_t)c * HD4 + lane];

    float gws;
    gws  = (x.x * g.x) * fmaf(cc, Wp.x, dc * W.x);
    gws += (x.y * g.y) * fmaf(cc, Wp.y, dc * W.y);
    gws += (x.z * g.z) * fmaf(cc, Wp.z, dc * W.z);
    gws += (x.w * g.w) * fmaf(cc, Wp.w, dc * W.w);
    float4 gx;
    gx.x = W.x * cc * g.x;
    gx.y = W.y * cc * g.y;
    gx.z = W.z * cc * g.z;
    gx.w = W.w * cc * g.w;
    red_add_v4((float*)(gxh + (size_t)r * HD4 + lane), gx);
#pragma unroll
    for (int o = 16; o > 0; o >>= 1) gws += __shfl_xor_sync(0xffffffffu, gws, o);
    if (lane == 0) g_gradw[e] += gws;   // unique writer per edge per pass
}

// ---------------- forces ----------------
__global__ void k_force(const int* __restrict__ ei, float* __restrict__ fout, int E) {
    int e = blockIdx.x * blockDim.x + threadIdx.x;
    if (e >= E) return;
    float w = g_w[e];
    float s = (w > 1e-12f) ? (g_gradw[e] / w) : 0.0f;
    int r = ei[e], c = ei[E + e];
#pragma unroll
    for (int d = 0; d < 3; d++) {
        float f = s * g_vec[(size_t)e * 3 + d];
        atomicAdd(&fout[r * 3 + d], -f);
        atomicAdd(&fout[c * 3 + d],  f);
    }
}

// ---------------- readout as blocked GEMM (64-row blocks): energy + grad_hL ----------------
__device__ __forceinline__ void load_A_g64(const float* __restrict__ A, float As[16][68],
                                           int bm, int k0, int tid, int N) {
#pragma unroll
    for (int i = 0; i < 4; i++) {
        int idx = tid + i * 256;
        int kk = idx & 15, rr = idx >> 4;
        int gm = bm + rr;
        As[kk][rr] = (gm < N) ? A[(size_t)gm * HD + k0 + kk] : 0.0f;
    }
}
__global__ __launch_bounds__(256)
void k_readout(const float* __restrict__ hL,
               const float* __restrict__ o1w, const float* __restrict__ o1b,
               const float* __restrict__ o2w, const float* __restrict__ o2b,
               float* __restrict__ gh, float* __restrict__ out_e, int N) {
    __shared__ float As[16][68];
    __shared__ float Bs[16][132];
    __shared__ float Us[64][68];
    __shared__ float yp[16][68];
    __shared__ float ys[64];
    int bm = blockIdx.x * 64;
    int tid = threadIdx.x, tx = tid & 15, ty = tid >> 4;

    // ---- stage 1: u = h @ o1w (64x64, K=128) ----
    float acc[4][4];
#pragma unroll
    for (int i = 0; i < 4; i++)
#pragma unroll
        for (int j = 0; j < 4; j++) acc[i][j] = 0.0f;
    for (int k0 = 0; k0 < HD; k0 += 16) {
        load_A_g64(hL, As, bm, k0, tid, N);
#pragma unroll
        for (int i = 0; i < 4; i++) {
            int idx = tid + i * 256;
            int kk = idx >> 6, nn = idx & 63;
            Bs[kk][nn] = o1w[(size_t)(k0 + kk) * 64 + nn];
        }
        __syncthreads();
#pragma unroll
        for (int k = 0; k < 16; k++) {
            float ra[4], rb[4];
#pragma unroll
            for (int i = 0; i < 4; i++) ra[i] = As[k][ty * 4 + i];
#pragma unroll
            for (int j = 0; j < 4; j++) rb[j] = Bs[k][tx * 4 + j];
#pragma unroll
            for (int i = 0; i < 4; i++)
#pragma unroll
                for (int j = 0; j < 4; j++) acc[i][j] = fmaf(ra[i], rb[j], acc[i][j]);
        }
        __syncthreads();
    }
#pragma unroll
    for (int i = 0; i < 4; i++) {
        int row = ty * 4 + i;
        float rs = 0.0f;
#pragma unroll
        for (int j = 0; j < 4; j++) {
            int cidx = tx * 4 + j;
            float u = acc[i][j] + o1b[cidx];
            float w2v = o2w[cidx];
            Us[row][cidx] = w2v * sigf(u);
            rs = fmaf(sspf(u), w2v, rs);
        }
        yp[tx][row] = rs;
    }
    __syncthreads();
    if (tid < 64) {
        float v = 0.0f;
#pragma unroll
        for (int p = 0; p < 16; p++) v += yp[p][tid];
        ys[tid] = (bm + tid < N) ? (v + o2b[0]) : 0.0f;
    }
    __syncthreads();
    if (tid == 0) {
        float s = 0.0f;
        for (int rr = 0; rr < 64; rr++) s += ys[rr];
        atomicAdd(out_e, s);
    }

    // ---- stage 2: gh = Us(Gu) @ o1w^T (64x128, K=64) ----
    float acc2[4][8];
#pragma unroll
    for (int i = 0; i < 4; i++)
#pragma unroll
        for (int j = 0; j < 8; j++) acc2[i][j] = 0.0f;
    for (int j0 = 0; j0 < 64; j0 += 16) {
        __syncthreads();
#pragma unroll
        for (int i = 0; i < 8; i++) {
            int idx = tid + i * 256;
            int jj = idx & 15, k = idx >> 4;
            Bs[jj][k] = o1w[(size_t)k * 64 + j0 + jj];
        }
        __syncthreads();
#pragma unroll
        for (int jj = 0; jj < 16; jj++) {
            float ra[4];
#pragma unroll
            for (int i = 0; i < 4; i++) ra[i] = Us[ty * 4 + i][j0 + jj];
            float4 b0 = *(const float4*)&Bs[jj][tx * 8];
            float4 b1 = *(const float4*)&Bs[jj][tx * 8 + 4];
            float rb[8] = {b0.x, b0.y, b0.z, b0.w, b1.x, b1.y, b1.z, b1.w};
#pragma unroll
            for (int i = 0; i < 4; i++)
#pragma unroll
                for (int j = 0; j < 8; j++) acc2[i][j] = fmaf(ra[i], rb[j], acc2[i][j]);
        }
    }
#pragma unroll
    for (int i = 0; i < 4; i++) {
        int gm = bm + ty * 4 + i;
        if (gm >= N) continue;
        float4 v0, v1;
        v0.x=acc2[i][0]; v0.y=acc2[i][1]; v0.z=acc2[i][2]; v0.w=acc2[i][3];
        v1.x=acc2[i][4]; v1.y=acc2[i][5]; v1.z=acc2[i][6]; v1.w=acc2[i][7];
        *(float4*)&gh[(size_t)gm * HD + tx * 8]     = v0;
        *(float4*)&gh[(size_t)gm * HD + tx * 8 + 4] = v1;
    }
}

// ---------------- launch ----------------
extern "C" void kernel_launch(void* const* d_in, const int* in_sizes, int n_in,
                              void* d_out, int out_size) {
    const int*   z    = (const int*)  d_in[0];
    const float* pos  = (const float*)d_in[1];
    const int*   ei   = (const int*)  d_in[2];
    const float* off  = (const float*)d_in[3];
    const float* cell = (const float*)d_in[4];
    const float* emb  = (const float*)d_in[5];
    const float* mw1  = (const float*)d_in[6];
    const float* mb1  = (const float*)d_in[7];
    const float* mw2  = (const float*)d_in[8];
    const float* mb2  = (const float*)d_in[9];
    const float* cw1  = (const float*)d_in[10];
    const float* cw2  = (const float*)d_in[11];
    const float* cb2  = (const float*)d_in[12];
    const float* lw   = (const float*)d_in[13];
    const float* lb   = (const float*)d_in[14];
    const float* o1w  = (const float*)d_in[15];
    const float* o1b  = (const float*)d_in[16];
    const float* o2w  = (const float*)d_in[17];
    const float* o2b  = (const float*)d_in[18];
    int N = in_sizes[0];
    int E = in_sizes[2] / 2;
    float* out = (float*)d_out;
    float* fout = out + 1;

    float4 *p_xh4, *p_agg4, *p_gxh4;
    float *p_eag, *p_deag, *p_t1g, *p_dt1g, *p_Wt32, *p_Wpt32;
    __half *p_Wth, *p_Wpth;
    float *p_h, *p_m, *p_gh, *p_gradw;
    cudaGetSymbolAddress((void**)&p_Wt32,   g_Wt32);
    cudaGetSymbolAddress((void**)&p_Wpt32,  g_Wpt32);
    cudaGetSymbolAddress((void**)&p_Wth,    g_Wth);
    cudaGetSymbolAddress((void**)&p_Wpth,   g_Wpth);
    cudaGetSymbolAddress((void**)&p_eag,    g_eag);
    cudaGetSymbolAddress((void**)&p_deag,   g_deag);
    cudaGetSymbolAddress((void**)&p_t1g,    g_t1g);
    cudaGetSymbolAddress((void**)&p_dt1g,   g_dt1g);
    cudaGetSymbolAddress((void**)&p_h,      g_h);
    cudaGetSymbolAddress((void**)&p_xh4,    g_xh4);
    cudaGetSymbolAddress((void**)&p_m,      g_m);
    cudaGetSymbolAddress((void**)&p_agg4,   g_agg4);
    cudaGetSymbolAddress((void**)&p_gh,     g_gh);
    cudaGetSymbolAddress((void**)&p_gxh4,   g_gxh4);
    cudaGetSymbolAddress((void**)&p_gradw,  g_gradw);

    cudaMemsetAsync(out, 0, (size_t)out_size * sizeof(float), 0);
    cudaMemsetAsync(p_gradw, 0, (size_t)E * sizeof(float), 0);
    cudaMemsetAsync(p_agg4, 0, (size_t)N * HD * sizeof(float), 0);  // once; fused_fwd re-zeros

    k_edge_geom<<<(E + 255) / 256, 256>>>(pos, ei, off, cell, E);
    k_h0<<<(N * HD + 255) / 256, 256>>>(z, emb, p_h, N);
    k_tab_ea<<<(NGRID * GD + 255) / 256, 256>>>();

    const size_t sT = (size_t)NGRID * HD;
    dim3 gridTab(HD / 64, NGRID / 64, LD);
    dim3 gridXh0(HD / 64, (N + 63) / 64, 1);
    int nodeBlocks32 = (N + 31) / 32;
    int nodeBlocks64 = (N + 63) / 64;
    int scat_blocks = (int)(((size_t)E * 32 + 255) / 256);

    // ------- build filter tables W(w), W'(w), all layers batched; convert to fp16 -------
    k_gemm<false,0,0><<<gridTab, 256>>>(p_eag, mw1, mb1, nullptr, nullptr, p_t1g,
                                        NGRID, HD, GD, 0, (size_t)GD*HD, HD, sT);
    k_gemm<false,0,0><<<gridTab, 256>>>(p_deag, mw1, nullptr, nullptr, nullptr, p_dt1g,
                                        NGRID, HD, GD, 0, (size_t)GD*HD, 0, sT);
    k_gemm<false,1,0><<<gridTab, 256>>>(p_t1g, mw2, mb2, nullptr, nullptr, p_Wt32,
                                        NGRID, HD, HD, sT, (size_t)HD*HD, HD, sT);
    k_gemm<false,2,0><<<gridTab, 256>>>(p_dt1g, mw2, nullptr, p_t1g, nullptr, p_Wpt32,
                                        NGRID, HD, HD, sT, (size_t)HD*HD, 0, sT);
    size_t tabN = (size_t)LD * NGRID * HD;
    k_cvt_h<<<(int)((tabN + 255) / 256), 256>>>(p_Wt32, p_Wpt32, p_Wth, p_Wpth, tabN);

    // ------- forward -------
    k_gemm<false,0,0><<<gridXh0, 256>>>(p_h, cw1, nullptr, nullptr, nullptr, (float*)p_xh4,
                                        N, HD, HD, 0, 0, 0, 0);
    for (int i = 0; i < LD; i++) {
        const __half* Wth = p_Wth + (size_t)i * NGRID * HD;
        float4* xh = p_xh4 + (size_t)i * N * HD4;
        float* hi = p_h + (size_t)i * N * HD;
        float* hn = p_h + (size_t)(i + 1) * N * HD;
        float* mm = p_m + (size_t)i * N * HD;
        const float* cw1n = (i + 1 < LD) ? cw1 + (size_t)(i + 1) * HD * HD : nullptr;
        float* xhn = (i + 1 < LD) ? (float*)(p_xh4 + (size_t)(i + 1) * N * HD4) : nullptr;

        k_scatter_fwd<<<scat_blocks, 256>>>(xh, Wth, ei, p_agg4, E);
        k_fused_fwd<<<nodeBlocks32, 256>>>((float*)p_agg4, cw2 + (size_t)i*HD*HD, cb2 + i*HD,
                                           lw + (size_t)i*HD*HD, lb + i*HD, hi, cw1n,
                                           mm, hn, xhn, N);
    }

    // ------- readout (energy + grad_h_L) -------
    k_readout<<<nodeBlocks64, 256>>>(p_h + (size_t)LD * N * HD, o1w, o1b, o2w, o2b,
                                     p_gh, out, N);

    // ------- backward -------
    for (int j = LD - 1; j >= 0; j--) {
        const __half* Wth  = p_Wth  + (size_t)j * NGRID * HD;
        const __half* Wpth = p_Wpth + (size_t)j * NGRID * HD;
        float4* xh = p_xh4 + (size_t)j * N * HD4;
        float* mm = p_m + (size_t)j * N * HD;
        int has_gxh = (j < LD - 1) ? 1 : 0;
        const float* cw1n = (j < LD - 1) ? cw1 + (size_t)(j + 1) * HD * HD : nullptr;

        k_fused_bwd<<<nodeBlocks32, 256>>>(p_gh, (float*)p_gxh4, has_gxh, cw1n,
                                           lw + (size_t)j*HD*HD, mm, cw2 + (size_t)j*HD*HD,
                                           (float*)p_agg4, N);
        k_scatter_bwd<<<scat_blocks, 256>>>(xh, Wth, Wpth, p_agg4, ei, p_gxh4, E);
    }

    // ------- forces -------
    k_force<<<(E + 255) / 256, 256>>>(ei, fout, E);
}

// round 15
// speedup vs baseline: 1.1713x; 1.1713x over previous
#include <cuda_runtime.h>
#include <cuda_fp16.h>
#include <math.h>
#include <stdint.h>

// Problem constants (fixed dataset)
#define NATOMS_MAX 10000
#define NEDGE_MAX  320000
#define HD 128      // hidden = filter dim
#define HD4 (HD/4)
#define GD 50       // gaussians
#define LD 6        // layers

#define NGRID 2048
#define WMAX  6.0f
#define HSTEP (WMAX / (float)(NGRID - 1))
#define INVH  ((float)(NGRID - 1) / WMAX)

#define DELTA   (4.0f/49.0f)
#define COEF    (-0.5f/(DELTA*DELTA))
#define TWOC    (2.0f*COEF)
#define PI_F    3.14159265358979323846f
#define LN2_F   0.6931471805599453f

// ---------------- scratch (static device globals; no allocation) ----------------
__device__ float g_vec[(size_t)NEDGE_MAX*3];
__device__ float g_w[NEDGE_MAX];
__device__ float4 g_epk[NEDGE_MAX];   // packed per-edge: {t, C, dC, bitcast(r)}
__device__ float g_gradw[NEDGE_MAX];

// filter tables: fp32 staging (GEMM out) + fp16 final
__device__ float g_Wt32 [(size_t)LD*NGRID*HD];
__device__ float g_Wpt32[(size_t)LD*NGRID*HD];
__device__ __half g_Wth [(size_t)LD*NGRID*HD];
__device__ __half g_Wpth[(size_t)LD*NGRID*HD];
__device__ float g_eag  [(size_t)NGRID*GD];
__device__ float g_deag [(size_t)NGRID*GD];
__device__ float g_t1g  [(size_t)LD*NGRID*HD];
__device__ float g_dt1g [(size_t)LD*NGRID*HD];

__device__ float  g_h  [(size_t)(LD+1)*NATOMS_MAX*HD];
__device__ float4 g_xh4[(size_t)LD*NATOMS_MAX*HD4];
__device__ float  g_m  [(size_t)LD*NATOMS_MAX*HD];
__device__ float4 g_agg4[(size_t)NATOMS_MAX*HD4];
__device__ float  g_gh [(size_t)NATOMS_MAX*HD];
__device__ float4 g_gxh4[(size_t)NATOMS_MAX*HD4];

// ---------------- math helpers ----------------
__device__ __forceinline__ float sspf(float x) {
    return fmaxf(x, 0.0f) + log1pf(expf(-fabsf(x))) - LN2_F;
}
__device__ __forceinline__ float sigf(float x) {
    return 1.0f / (1.0f + expf(-x));
}
__device__ __forceinline__ void red_add_v4(float* p, float4 v) {
    asm volatile("red.global.add.v4.f32 [%0], {%1,%2,%3,%4};"
                 :: "l"(p), "f"(v.x), "f"(v.y), "f"(v.z), "f"(v.w) : "memory");
}
// lerp a 128-ch fp16 table row pair at (i0, f); lane handles 4 channels
__device__ __forceinline__ float4 lerp_row_h(const __half* __restrict__ tab,
                                             int i0, float f, int lane) {
    const char* base = (const char*)(tab + (size_t)i0 * HD + lane * 4);
    uint2 ua = *(const uint2*)base;
    uint2 ub = *(const uint2*)(base + HD * 2);
    float2 a0 = __half22float2(*(__half2*)&ua.x);
    float2 a1 = __half22float2(*(__half2*)&ua.y);
    float2 b0 = __half22float2(*(__half2*)&ub.x);
    float2 b1 = __half22float2(*(__half2*)&ub.y);
    float4 o;
    o.x = fmaf(f, b0.x - a0.x, a0.x);
    o.y = fmaf(f, b0.y - a0.y, a0.y);
    o.z = fmaf(f, b1.x - a1.x, a1.x);
    o.w = fmaf(f, b1.y - a1.y, a1.y);
    return o;
}

// ---------------- edge geometry (+ packed params) ----------------
__global__ void k_edge_geom(const float* __restrict__ pos, const int* __restrict__ ei,
                            const float* __restrict__ off, const float* __restrict__ cell, int E) {
    int e = blockIdx.x * blockDim.x + threadIdx.x;
    if (e >= E) return;
    int r = ei[e], c = ei[E + e];
    float o0 = off[e*3+0], o1 = off[e*3+1], o2 = off[e*3+2];
    float v0 = pos[r*3+0] - pos[c*3+0] + o0*cell[0] + o1*cell[3] + o2*cell[6];
    float v1 = pos[r*3+1] - pos[c*3+1] + o0*cell[1] + o1*cell[4] + o2*cell[7];
    float v2 = pos[r*3+2] - pos[c*3+2] + o0*cell[2] + o1*cell[5] + o2*cell[8];
    float w = sqrtf(v0*v0 + v1*v1 + v2*v2);
    g_vec[(size_t)e*3+0] = v0; g_vec[(size_t)e*3+1] = v1; g_vec[(size_t)e*3+2] = v2;
    g_w[e] = w;
    float a = w * (PI_F / 4.0f);
    float C  = 0.5f * (cosf(a) + 1.0f);
    float dC = -0.5f * sinf(a) * (PI_F / 4.0f);
    float t  = fminf(w, WMAX) * INVH;
    g_epk[e] = make_float4(t, C, dC, __int_as_float(r));
}

// ---------------- gaussian grid (once) ----------------
__global__ void k_tab_ea() {
    int idx = blockIdx.x * blockDim.x + threadIdx.x;
    if (idx >= NGRID * GD) return;
    int g = idx / GD, j = idx % GD;
    float w = (float)g * HSTEP;
    float d = w - (float)j * DELTA;
    float ea = expf(COEF * d * d);
    g_eag[idx]  = ea;
    g_deag[idx] = TWOC * d * ea;
}

__global__ void k_h0(const int* __restrict__ z, const float* __restrict__ emb,
                     float* __restrict__ h, int N) {
    int idx = blockIdx.x * blockDim.x + threadIdx.x;
    if (idx >= N * HD) return;
    int n = idx >> 7, k = idx & 127;
    h[idx] = emb[(size_t)z[n] * HD + k];
}

__global__ void k_cvt_h(const float* __restrict__ a, const float* __restrict__ b,
                        __half* __restrict__ ha, __half* __restrict__ hb, size_t n) {
    size_t i = (size_t)blockIdx.x * blockDim.x + threadIdx.x;
    if (i >= n) return;
    ha[i] = __float2half_rn(a[i]);
    hb[i] = __float2half_rn(b[i]);
}

// ---------------- tiled fp32 GEMM (tables + xh0) ----------------
template<bool TB, int AOP, int EPI>
__global__ __launch_bounds__(256)
void k_gemm(const float* __restrict__ A, const float* __restrict__ B,
            const float* __restrict__ bias, const float* __restrict__ add_,
            const float* __restrict__ aux, float* __restrict__ Co,
            int M, int Nn, int K,
            size_t sA, size_t sB, size_t sBias, size_t sC) {
    const int BM = 64, BN = 64, BK = 16;
    int zb = blockIdx.z;
    A  += (size_t)zb * sA;
    B  += (size_t)zb * sB;
    Co += (size_t)zb * sC;
    const float* bi = bias ? bias + (size_t)zb * sBias : nullptr;
    const float* ax2 = (AOP == 2) ? add_ + (size_t)zb * sA : nullptr;

    __shared__ float As[BK][BM + 4];
    __shared__ float Bs[BK][BN + 4];
    int bm = blockIdx.y * BM, bn = blockIdx.x * BN;
    int tid = threadIdx.x;
    int tx = tid & 15, ty = tid >> 4;
    int la_k = tid & 15, la_r = tid >> 4;
    float acc[4][4];
#pragma unroll
    for (int i = 0; i < 4; i++)
#pragma unroll
        for (int j = 0; j < 4; j++) acc[i][j] = 0.0f;

    for (int k0 = 0; k0 < K; k0 += BK) {
#pragma unroll
        for (int i = 0; i < 4; i++) {
            int m = bm + la_r + i * 16;
            int k = k0 + la_k;
            float v = 0.0f;
            if (m < M && k < K) {
                v = A[(size_t)m * K + k];
                if (AOP == 1) v = sspf(v);
                if (AOP == 2) v *= sigf(ax2[(size_t)m * K + k]);
            }
            As[la_k][la_r + i * 16] = v;
        }
#pragma unroll
        for (int i = 0; i < 4; i++) {
            int idx = tid + i * 256;
            int kk = idx >> 6;
            int nn = idx & 63;
            int k = k0 + kk, n = bn + nn;
            float v = 0.0f;
            if (k < K && n < Nn) v = TB ? B[(size_t)n * K + k] : B[(size_t)k * Nn + n];
            Bs[kk][nn] = v;
        }
        __syncthreads();
#pragma unroll
        for (int k = 0; k < BK; k++) {
            float ra[4], rb[4];
#pragma unroll
            for (int i = 0; i < 4; i++) ra[i] = As[k][ty * 4 + i];
#pragma unroll
            for (int j = 0; j < 4; j++) rb[j] = Bs[k][tx * 4 + j];
#pragma unroll
            for (int i = 0; i < 4; i++)
#pragma unroll
                for (int j = 0; j < 4; j++) acc[i][j] = fmaf(ra[i], rb[j], acc[i][j]);
        }
        __syncthreads();
    }
#pragma unroll
    for (int i = 0; i < 4; i++) {
        int m = bm + ty * 4 + i;
        if (m >= M) continue;
#pragma unroll
        for (int j = 0; j < 4; j++) {
            int n = bn + tx * 4 + j;
            if (n >= Nn) continue;
            float v = acc[i][j];
            if (bi) v += bi[n];
            size_t o = (size_t)m * Nn + n;
            if (EPI == 1) v += add_[o];
            if (EPI == 2) v *= sigf(aux[o]);
            Co[o] = v;
        }
    }
}

// ============ fused multi-stage node kernels (64-row blocks, 256 thr) ============
__device__ __forceinline__ void load_B_nt(const float* __restrict__ B, float Bs[16][132],
                                          int k0, int tid) {
#pragma unroll
    for (int i = 0; i < 8; i++) {
        int idx = tid + i * 256;
        int kk = idx >> 7, nn = idx & 127;
        Bs[kk][nn] = B[(size_t)(k0 + kk) * HD + nn];
    }
}
__device__ __forceinline__ void load_B_t(const float* __restrict__ B, float Bs[16][132],
                                         int k0, int tid) {
#pragma unroll
    for (int i = 0; i < 8; i++) {
        int idx = tid + i * 256;
        int kk = idx & 15, nn = idx >> 4;
        Bs[kk][nn] = B[(size_t)nn * HD + (k0 + kk)];
    }
}
__device__ __forceinline__ void fma_as(const float As[16][68], const float Bs[16][132],
                                       float acc[4][8], int tx, int ty) {
#pragma unroll
    for (int k = 0; k < 16; k++) {
        float4 a  = *(const float4*)&As[k][ty * 4];
        float4 b0 = *(const float4*)&Bs[k][tx * 8];
        float4 b1 = *(const float4*)&Bs[k][tx * 8 + 4];
        float ra[4] = {a.x, a.y, a.z, a.w};
        float rb[8] = {b0.x, b0.y, b0.z, b0.w, b1.x, b1.y, b1.z, b1.w};
#pragma unroll
        for (int i = 0; i < 4; i++)
#pragma unroll
            for (int j = 0; j < 8; j++) acc[i][j] = fmaf(ra[i], rb[j], acc[i][j]);
    }
}
__device__ __forceinline__ void fma_ms(const float Ms[64][132], const float Bs[16][132],
                                       float acc[4][8], int k0, int tx, int ty) {
#pragma unroll
    for (int k = 0; k < 16; k++) {
        float ra[4];
#pragma unroll
        for (int i = 0; i < 4; i++) ra[i] = Ms[ty * 4 + i][k0 + k];
        float4 b0 = *(const float4*)&Bs[k][tx * 8];
        float4 b1 = *(const float4*)&Bs[k][tx * 8 + 4];
        float rb[8] = {b0.x, b0.y, b0.z, b0.w, b1.x, b1.y, b1.z, b1.w};
#pragma unroll
        for (int i = 0; i < 4; i++)
#pragma unroll
            for (int j = 0; j < 8; j++) acc[i][j] = fmaf(ra[i], rb[j], acc[i][j]);
    }
}
__device__ __forceinline__ void load_A_g(const float* __restrict__ A, float As[16][68],
                                         int bm, int k0, int tid, int N) {
#pragma unroll
    for (int i = 0; i < 4; i++) {
        int idx = tid + i * 256;
        int kk = idx & 15, rr = idx >> 4;
        int gm = bm + rr;
        As[kk][rr] = (gm < N) ? A[(size_t)gm * HD + k0 + kk] : 0.0f;
    }
}
__device__ __forceinline__ void zero_acc(float acc[4][8]) {
#pragma unroll
    for (int i = 0; i < 4; i++)
#pragma unroll
        for (int j = 0; j < 8; j++) acc[i][j] = 0.0f;
}

// fused forward per layer: m = agg@w2+b2 ; hn = hi + ssp(m)@lw+lb ; xhn = hn@cw1n (optional)
// ALSO re-zeros agg rows after consuming (ready for next layer's scatter).
__global__ __launch_bounds__(256)
void k_fused_fwd(float* __restrict__ agg, const float* __restrict__ w2,
                 const float* __restrict__ b2, const float* __restrict__ lw,
                 const float* __restrict__ lb, const float* __restrict__ hi,
                 const float* __restrict__ cw1n,
                 float* __restrict__ m_out, float* __restrict__ hn,
                 float* __restrict__ xhn, int N) {
    __shared__ float As[16][68];
    __shared__ float Bs[16][132];
    __shared__ float Ms[64][132];
    int bm = blockIdx.x * 64;
    int tid = threadIdx.x, tx = tid & 15, ty = tid >> 4;
    float acc[4][8];
    zero_acc(acc);

    // stage 1: m = agg @ w2
    for (int k0 = 0; k0 < HD; k0 += 16) {
        load_A_g(agg, As, bm, k0, tid, N);
        load_B_nt(w2, Bs, k0, tid);
        __syncthreads();
        fma_as(As, Bs, acc, tx, ty);
        __syncthreads();
    }
    const float4 z4 = make_float4(0.f, 0.f, 0.f, 0.f);
#pragma unroll
    for (int i = 0; i < 4; i++) {
        int gm = bm + ty * 4 + i;
        float4 v0, v1;
        float* vv0 = (float*)&v0; float* vv1 = (float*)&v1;
#pragma unroll
        for (int j = 0; j < 8; j++) {
            int c = tx * 8 + j;
            float v = acc[i][j] + b2[c];
            Ms[ty * 4 + i][c] = sspf(v);
            if (j < 4) vv0[j] = v; else vv1[j - 4] = v;
            acc[i][j] = 0.0f;
        }
        if (gm < N) {
            *(float4*)&m_out[(size_t)gm * HD + tx * 8]     = v0;
            *(float4*)&m_out[(size_t)gm * HD + tx * 8 + 4] = v1;
            // re-zero agg for next layer's scatter
            *(float4*)&agg[(size_t)gm * HD + tx * 8]     = z4;
            *(float4*)&agg[(size_t)gm * HD + tx * 8 + 4] = z4;
        }
    }
    __syncthreads();

    // stage 2: hn = Ms(ssp(m)) @ lw + lb + hi
    for (int k0 = 0; k0 < HD; k0 += 16) {
        load_B_nt(lw, Bs, k0, tid);
        __syncthreads();
        fma_ms(Ms, Bs, acc, k0, tx, ty);
        __syncthreads();
    }
#pragma unroll
    for (int i = 0; i < 4; i++) {
        int gm = bm + ty * 4 + i;
        float hiv[8];
        if (gm < N) {
            float4 a = *(const float4*)&hi[(size_t)gm * HD + tx * 8];
            float4 b = *(const float4*)&hi[(size_t)gm * HD + tx * 8 + 4];
            hiv[0]=a.x; hiv[1]=a.y; hiv[2]=a.z; hiv[3]=a.w;
            hiv[4]=b.x; hiv[5]=b.y; hiv[6]=b.z; hiv[7]=b.w;
        } else {
#pragma unroll
            for (int j = 0; j < 8; j++) hiv[j] = 0.0f;
        }
        float4 v0, v1;
        float* vv0 = (float*)&v0; float* vv1 = (float*)&v1;
#pragma unroll
        for (int j = 0; j < 8; j++) {
            int c = tx * 8 + j;
            float v = acc[i][j] + lb[c] + hiv[j];
            Ms[ty * 4 + i][c] = v;    // safe: all stage-2 reads done (last sync)
            if (j < 4) vv0[j] = v; else vv1[j - 4] = v;
            acc[i][j] = 0.0f;
        }
        if (gm < N) {
            *(float4*)&hn[(size_t)gm * HD + tx * 8]     = v0;
            *(float4*)&hn[(size_t)gm * HD + tx * 8 + 4] = v1;
        }
    }
    if (!cw1n) return;
    __syncthreads();

    // stage 3: xhn = Ms(hn) @ cw1n
    for (int k0 = 0; k0 < HD; k0 += 16) {
        load_B_nt(cw1n, Bs, k0, tid);
        __syncthreads();
        fma_ms(Ms, Bs, acc, k0, tx, ty);
        __syncthreads();
    }
#pragma unroll
    for (int i = 0; i < 4; i++) {
        int gm = bm + ty * 4 + i;
        if (gm >= N) continue;
        float4 v0, v1;
        v0.x=acc[i][0]; v0.y=acc[i][1]; v0.z=acc[i][2]; v0.w=acc[i][3];
        v1.x=acc[i][4]; v1.y=acc[i][5]; v1.z=acc[i][6]; v1.w=acc[i][7];
        *(float4*)&xhn[(size_t)gm * HD + tx * 8]     = v0;
        *(float4*)&xhn[(size_t)gm * HD + tx * 8 + 4] = v1;
    }
}

// fused backward per layer j; ALSO re-zeros gxh rows for the following scatter_bwd.
__global__ __launch_bounds__(256)
void k_fused_bwd(float* __restrict__ gh, float* __restrict__ gxh, int has_gxh,
                 const float* __restrict__ cw1n, const float* __restrict__ lw,
                 const float* __restrict__ m, const float* __restrict__ w2,
                 float* __restrict__ gagg, int N) {
    __shared__ float As[16][68];
    __shared__ float Bs[16][132];
    __shared__ float Ms[64][132];
    int bm = blockIdx.x * 64;
    int tid = threadIdx.x, tx = tid & 15, ty = tid >> 4;
    float acc[4][8];
    zero_acc(acc);

    // stage 0: gh += gxh @ cw1n^T
    if (has_gxh) {
        for (int k0 = 0; k0 < HD; k0 += 16) {
            load_A_g(gxh, As, bm, k0, tid, N);
            load_B_t(cw1n, Bs, k0, tid);
            __syncthreads();
            fma_as(As, Bs, acc, tx, ty);
            __syncthreads();
        }
    }
    const float4 z4 = make_float4(0.f, 0.f, 0.f, 0.f);
#pragma unroll
    for (int i = 0; i < 4; i++) {
        int gm = bm + ty * 4 + i;
        float ghv[8];
        if (gm < N) {
            float4 a = *(const float4*)&gh[(size_t)gm * HD + tx * 8];
            float4 b = *(const float4*)&gh[(size_t)gm * HD + tx * 8 + 4];
            ghv[0]=a.x; ghv[1]=a.y; ghv[2]=a.z; ghv[3]=a.w;
            ghv[4]=b.x; ghv[5]=b.y; ghv[6]=b.z; ghv[7]=b.w;
        } else {
#pragma unroll
            for (int j = 0; j < 8; j++) ghv[j] = 0.0f;
        }
        float4 v0, v1;
        float* vv0 = (float*)&v0; float* vv1 = (float*)&v1;
#pragma unroll
        for (int j = 0; j < 8; j++) {
            int c = tx * 8 + j;
            float v = acc[i][j] + ghv[j];
            Ms[ty * 4 + i][c] = v;
            if (j < 4) vv0[j] = v; else vv1[j - 4] = v;
            acc[i][j] = 0.0f;
        }
        if (gm < N) {
            if (has_gxh) {
                *(float4*)&gh[(size_t)gm * HD + tx * 8]     = v0;
                *(float4*)&gh[(size_t)gm * HD + tx * 8 + 4] = v1;
            }
            // re-zero gxh for this layer's scatter_bwd accumulation
            *(float4*)&gxh[(size_t)gm * HD + tx * 8]     = z4;
            *(float4*)&gxh[(size_t)gm * HD + tx * 8 + 4] = z4;
        }
    }
    __syncthreads();

    // stage 1: t = Ms(gh) @ lw^T, gate by sigmoid(m)
    for (int k0 = 0; k0 < HD; k0 += 16) {
        load_B_t(lw, Bs, k0, tid);
        __syncthreads();
        fma_ms(Ms, Bs, acc, k0, tx, ty);
        __syncthreads();
    }
#pragma unroll
    for (int i = 0; i < 4; i++) {
        int gm = bm + ty * 4 + i;
        float mv[8];
        if (gm < N) {
            float4 a = *(const float4*)&m[(size_t)gm * HD + tx * 8];
            float4 b = *(const float4*)&m[(size_t)gm * HD + tx * 8 + 4];
            mv[0]=a.x; mv[1]=a.y; mv[2]=a.z; mv[3]=a.w;
            mv[4]=b.x; mv[5]=b.y; mv[6]=b.z; mv[7]=b.w;
        } else {
#pragma unroll
            for (int j = 0; j < 8; j++) mv[j] = 0.0f;
        }
#pragma unroll
        for (int j = 0; j < 8; j++) {
            int c = tx * 8 + j;
            Ms[ty * 4 + i][c] = acc[i][j] * sigf(mv[j]);
            acc[i][j] = 0.0f;
        }
    }
    __syncthreads();

    // stage 2: gagg = Ms(gn) @ w2^T (full overwrite)
    for (int k0 = 0; k0 < HD; k0 += 16) {
        load_B_t(w2, Bs, k0, tid);
        __syncthreads();
        fma_ms(Ms, Bs, acc, k0, tx, ty);
        __syncthreads();
    }
#pragma unroll
    for (int i = 0; i < 4; i++) {
        int gm = bm + ty * 4 + i;
        if (gm >= N) continue;
        float4 v0, v1;
        v0.x=acc[i][0]; v0.y=acc[i][1]; v0.z=acc[i][2]; v0.w=acc[i][3];
        v1.x=acc[i][4]; v1.y=acc[i][5]; v1.z=acc[i][6]; v1.w=acc[i][7];
        *(float4*)&gagg[(size_t)gm * HD + tx * 8]     = v0;
        *(float4*)&gagg[(size_t)gm * HD + tx * 8 + 4] = v1;
    }
}

// ---------------- scatter forward: warp per edge, fp16 table lerp, red.v4 ----------------
__global__ __launch_bounds__(256)
void k_scatter_fwd(const float4* __restrict__ xh, const __half* __restrict__ Wth,
                   const int* __restrict__ ei, float4* __restrict__ agg, int E) {
    int e = (int)(((size_t)blockIdx.x * blockDim.x + threadIdx.x) >> 5);
    int lane = threadIdx.x & 31;
    if (e >= E) return;
    float4 pk = g_epk[e];
    float t = pk.x, cc = pk.y;
    int r = __float_as_int(pk.w);
    int c = ei[E + e];
    int i0 = min((int)t, NGRID - 2);
    float f = t - (float)i0;
    float4 W = lerp_row_h(Wth, i0, f, lane);
    float4 x = xh[(size_t)r * HD4 + lane];
    float4 v;
    v.x = W.x * cc * x.x;
    v.y = W.y * cc * x.y;
    v.z = W.z * cc * x.z;
    v.w = W.w * cc * x.w;
    red_add_v4((float*)(agg + (size_t)c * HD4 + lane), v);
}

// ---------------- scatter backward: warp per edge ----------------
__global__ __launch_bounds__(256)
void k_scatter_bwd(const float4* __restrict__ xh, const __half* __restrict__ Wth,
                   const __half* __restrict__ Wpth,
                   const float4* __restrict__ gagg, const int* __restrict__ ei,
                   float4* __restrict__ gxh, int E) {
    int e = (int)(((size_t)blockIdx.x * blockDim.x + threadIdx.x) >> 5);
    int lane = threadIdx.x & 31;
    if (e >= E) return;
    float4 pk = g_epk[e];
    float t = pk.x, cc = pk.y, dc = pk.z;
    int r = __float_as_int(pk.w);
    int c = ei[E + e];
    int i0 = min((int)t, NGRID - 2);
    float f = t - (float)i0;
    float4 W  = lerp_row_h(Wth,  i0, f, lane);
    float4 Wp = lerp_row_h(Wpth, i0, f, lane);
    float4 x = xh[(size_t)r * HD4 + lane];
    float4 g = gagg[(size_t)c * HD4 + lane];

    float gws;
    gws  = (x.x * g.x) * fmaf(cc, Wp.x, dc * W.x);
    gws += (x.y * g.y) * fmaf(cc, Wp.y, dc * W.y);
    gws += (x.z * g.z) * fmaf(cc, Wp.z, dc * W.z);
    gws += (x.w * g.w) * fmaf(cc, Wp.w, dc * W.w);
    float4 gx;
    gx.x = W.x * cc * g.x;
    gx.y = W.y * cc * g.y;
    gx.z = W.z * cc * g.z;
    gx.w = W.w * cc * g.w;
    red_add_v4((float*)(gxh + (size_t)r * HD4 + lane), gx);
#pragma unroll
    for (int o = 16; o > 0; o >>= 1) gws += __shfl_xor_sync(0xffffffffu, gws, o);
    if (lane == 0) g_gradw[e] += gws;   // unique writer per edge per pass
}

// ---------------- forces ----------------
__global__ void k_force(const int* __restrict__ ei, float* __restrict__ fout, int E) {
    int e = blockIdx.x * blockDim.x + threadIdx.x;
    if (e >= E) return;
    float w = g_w[e];
    float s = (w > 1e-12f) ? (g_gradw[e] / w) : 0.0f;
    int r = ei[e], c = ei[E + e];
#pragma unroll
    for (int d = 0; d < 3; d++) {
        float f = s * g_vec[(size_t)e * 3 + d];
        atomicAdd(&fout[r * 3 + d], -f);
        atomicAdd(&fout[c * 3 + d],  f);
    }
}

// ---------------- readout as blocked GEMM (64-row blocks): energy + grad_hL ----------------
__global__ __launch_bounds__(256)
void k_readout(const float* __restrict__ hL,
               const float* __restrict__ o1w, const float* __restrict__ o1b,
               const float* __restrict__ o2w, const float* __restrict__ o2b,
               float* __restrict__ gh, float* __restrict__ out_e, int N) {
    __shared__ float As[16][68];
    __shared__ float Bs[16][132];
    __shared__ float Us[64][68];
    __shared__ float yp[16][68];
    __shared__ float ys[64];
    int bm = blockIdx.x * 64;
    int tid = threadIdx.x, tx = tid & 15, ty = tid >> 4;

    // ---- stage 1: u = h @ o1w (64x64, K=128) ----
    float acc[4][4];
#pragma unroll
    for (int i = 0; i < 4; i++)
#pragma unroll
        for (int j = 0; j < 4; j++) acc[i][j] = 0.0f;
    for (int k0 = 0; k0 < HD; k0 += 16) {
        load_A_g(hL, As, bm, k0, tid, N);
#pragma unroll
        for (int i = 0; i < 4; i++) {
            int idx = tid + i * 256;
            int kk = idx >> 6, nn = idx & 63;
            Bs[kk][nn] = o1w[(size_t)(k0 + kk) * 64 + nn];
        }
        __syncthreads();
#pragma unroll
        for (int k = 0; k < 16; k++) {
            float ra[4], rb[4];
#pragma unroll
            for (int i = 0; i < 4; i++) ra[i] = As[k][ty * 4 + i];
#pragma unroll
            for (int j = 0; j < 4; j++) rb[j] = Bs[k][tx * 4 + j];
#pragma unroll
            for (int i = 0; i < 4; i++)
#pragma unroll
                for (int j = 0; j < 4; j++) acc[i][j] = fmaf(ra[i], rb[j], acc[i][j]);
        }
        __syncthreads();
    }
#pragma unroll
    for (int i = 0; i < 4; i++) {
        int row = ty * 4 + i;
        float rs = 0.0f;
#pragma unroll
        for (int j = 0; j < 4; j++) {
            int cidx = tx * 4 + j;
            float u = acc[i][j] + o1b[cidx];
            float w2v = o2w[cidx];
            Us[row][cidx] = w2v * sigf(u);
            rs = fmaf(sspf(u), w2v, rs);
        }
        yp[tx][row] = rs;
    }
    __syncthreads();
    if (tid < 64) {
        float v = 0.0f;
#pragma unroll
        for (int p = 0; p < 16; p++) v += yp[p][tid];
        ys[tid] = (bm + tid < N) ? (v + o2b[0]) : 0.0f;
    }
    __syncthreads();
    if (tid == 0) {
        float s = 0.0f;
        for (int rr = 0; rr < 64; rr++) s += ys[rr];
        atomicAdd(out_e, s);
    }

    // ---- stage 2: gh = Us(Gu) @ o1w^T (64x128, K=64) ----
    float acc2[4][8];
    zero_acc(acc2);
    for (int j0 = 0; j0 < 64; j0 += 16) {
        __syncthreads();
#pragma unroll
        for (int i = 0; i < 8; i++) {
            int idx = tid + i * 256;
            int jj = idx & 15, k = idx >> 4;
            Bs[jj][k] = o1w[(size_t)k * 64 + j0 + jj];
        }
        __syncthreads();
#pragma unroll
        for (int jj = 0; jj < 16; jj++) {
            float ra[4];
#pragma unroll
            for (int i = 0; i < 4; i++) ra[i] = Us[ty * 4 + i][j0 + jj];
            float4 b0 = *(const float4*)&Bs[jj][tx * 8];
            float4 b1 = *(const float4*)&Bs[jj][tx * 8 + 4];
            float rb[8] = {b0.x, b0.y, b0.z, b0.w, b1.x, b1.y, b1.z, b1.w};
#pragma unroll
            for (int i = 0; i < 4; i++)
#pragma unroll
                for (int j = 0; j < 8; j++) acc2[i][j] = fmaf(ra[i], rb[j], acc2[i][j]);
        }
    }
#pragma unroll
    for (int i = 0; i < 4; i++) {
        int gm = bm + ty * 4 + i;
        if (gm >= N) continue;
        float4 v0, v1;
        v0.x=acc2[i][0]; v0.y=acc2[i][1]; v0.z=acc2[i][2]; v0.w=acc2[i][3];
        v1.x=acc2[i][4]; v1.y=acc2[i][5]; v1.z=acc2[i][6]; v1.w=acc2[i][7];
        *(float4*)&gh[(size_t)gm * HD + tx * 8]     = v0;
        *(float4*)&gh[(size_t)gm * HD + tx * 8 + 4] = v1;
    }
}

// ---------------- launch ----------------
extern "C" void kernel_launch(void* const* d_in, const int* in_sizes, int n_in,
                              void* d_out, int out_size) {
    const int*   z    = (const int*)  d_in[0];
    const float* pos  = (const float*)d_in[1];
    const int*   ei   = (const int*)  d_in[2];
    const float* off  = (const float*)d_in[3];
    const float* cell = (const float*)d_in[4];
    const float* emb  = (const float*)d_in[5];
    const float* mw1  = (const float*)d_in[6];
    const float* mb1  = (const float*)d_in[7];
    const float* mw2  = (const float*)d_in[8];
    const float* mb2  = (const float*)d_in[9];
    const float* cw1  = (const float*)d_in[10];
    const float* cw2  = (const float*)d_in[11];
    const float* cb2  = (const float*)d_in[12];
    const float* lw   = (const float*)d_in[13];
    const float* lb   = (const float*)d_in[14];
    const float* o1w  = (const float*)d_in[15];
    const float* o1b  = (const float*)d_in[16];
    const float* o2w  = (const float*)d_in[17];
    const float* o2b  = (const float*)d_in[18];
    int N = in_sizes[0];
    int E = in_sizes[2] / 2;
    float* out = (float*)d_out;
    float* fout = out + 1;

    float4 *p_xh4, *p_agg4, *p_gxh4;
    float *p_eag, *p_deag, *p_t1g, *p_dt1g, *p_Wt32, *p_Wpt32;
    __half *p_Wth, *p_Wpth;
    float *p_h, *p_m, *p_gh, *p_gradw;
    cudaGetSymbolAddress((void**)&p_Wt32,   g_Wt32);
    cudaGetSymbolAddress((void**)&p_Wpt32,  g_Wpt32);
    cudaGetSymbolAddress((void**)&p_Wth,    g_Wth);
    cudaGetSymbolAddress((void**)&p_Wpth,   g_Wpth);
    cudaGetSymbolAddress((void**)&p_eag,    g_eag);
    cudaGetSymbolAddress((void**)&p_deag,   g_deag);
    cudaGetSymbolAddress((void**)&p_t1g,    g_t1g);
    cudaGetSymbolAddress((void**)&p_dt1g,   g_dt1g);
    cudaGetSymbolAddress((void**)&p_h,      g_h);
    cudaGetSymbolAddress((void**)&p_xh4,    g_xh4);
    cudaGetSymbolAddress((void**)&p_m,      g_m);
    cudaGetSymbolAddress((void**)&p_agg4,   g_agg4);
    cudaGetSymbolAddress((void**)&p_gh,     g_gh);
    cudaGetSymbolAddress((void**)&p_gxh4,   g_gxh4);
    cudaGetSymbolAddress((void**)&p_gradw,  g_gradw);

    cudaMemsetAsync(out, 0, (size_t)out_size * sizeof(float), 0);
    cudaMemsetAsync(p_gradw, 0, (size_t)E * sizeof(float), 0);
    cudaMemsetAsync(p_agg4, 0, (size_t)N * HD * sizeof(float), 0);  // once; fused_fwd re-zeros

    k_edge_geom<<<(E + 255) / 256, 256>>>(pos, ei, off, cell, E);
    k_h0<<<(N * HD + 255) / 256, 256>>>(z, emb, p_h, N);
    k_tab_ea<<<(NGRID * GD + 255) / 256, 256>>>();

    const size_t sT = (size_t)NGRID * HD;
    dim3 gridTab(HD / 64, NGRID / 64, LD);
    dim3 gridXh0(HD / 64, (N + 63) / 64, 1);
    int nodeBlocks = (N + 63) / 64;
    int scat_blocks = (int)(((size_t)E * 32 + 255) / 256);

    // ------- build filter tables W(w), W'(w), all layers batched; convert to fp16 -------
    k_gemm<false,0,0><<<gridTab, 256>>>(p_eag, mw1, mb1, nullptr, nullptr, p_t1g,
                                        NGRID, HD, GD, 0, (size_t)GD*HD, HD, sT);
    k_gemm<false,0,0><<<gridTab, 256>>>(p_deag, mw1, nullptr, nullptr, nullptr, p_dt1g,
                                        NGRID, HD, GD, 0, (size_t)GD*HD, 0, sT);
    k_gemm<false,1,0><<<gridTab, 256>>>(p_t1g, mw2, mb2, nullptr, nullptr, p_Wt32,
                                        NGRID, HD, HD, sT, (size_t)HD*HD, HD, sT);
    k_gemm<false,2,0><<<gridTab, 256>>>(p_dt1g, mw2, nullptr, p_t1g, nullptr, p_Wpt32,
                                        NGRID, HD, HD, sT, (size_t)HD*HD, 0, sT);
    size_t tabN = (size_t)LD * NGRID * HD;
    k_cvt_h<<<(int)((tabN + 255) / 256), 256>>>(p_Wt32, p_Wpt32, p_Wth, p_Wpth, tabN);

    // ------- forward -------
    k_gemm<false,0,0><<<gridXh0, 256>>>(p_h, cw1, nullptr, nullptr, nullptr, (float*)p_xh4,
                                        N, HD, HD, 0, 0, 0, 0);
    for (int i = 0; i < LD; i++) {
        const __half* Wth = p_Wth + (size_t)i * NGRID * HD;
        float4* xh = p_xh4 + (size_t)i * N * HD4;
        float* hi = p_h + (size_t)i * N * HD;
        float* hn = p_h + (size_t)(i + 1) * N * HD;
        float* mm = p_m + (size_t)i * N * HD;
        const float* cw1n = (i + 1 < LD) ? cw1 + (size_t)(i + 1) * HD * HD : nullptr;
        float* xhn = (i + 1 < LD) ? (float*)(p_xh4 + (size_t)(i + 1) * N * HD4) : nullptr;

        k_scatter_fwd<<<scat_blocks, 256>>>(xh, Wth, ei, p_agg4, E);
        k_fused_fwd<<<nodeBlocks, 256>>>((float*)p_agg4, cw2 + (size_t)i*HD*HD, cb2 + i*HD,
                                         lw + (size_t)i*HD*HD, lb + i*HD, hi, cw1n,
                                         mm, hn, xhn, N);
    }

    // ------- readout (energy + grad_h_L) -------
    k_readout<<<nodeBlocks, 256>>>(p_h + (size_t)LD * N * HD, o1w, o1b, o2w, o2b,
                                   p_gh, out, N);

    // ------- backward -------
    for (int j = LD - 1; j >= 0; j--) {
        const __half* Wth  = p_Wth  + (size_t)j * NGRID * HD;
        const __half* Wpth = p_Wpth + (size_t)j * NGRID * HD;
        float4* xh = p_xh4 + (size_t)j * N * HD4;
        float* mm = p_m + (size_t)j * N * HD;
        int has_gxh = (j < LD - 1) ? 1 : 0;
        const float* cw1n = (j < LD - 1) ? cw1 + (size_t)(j + 1) * HD * HD : nullptr;

        k_fused_bwd<<<nodeBlocks, 256>>>(p_gh, (float*)p_gxh4, has_gxh, cw1n,
                                         lw + (size_t)j*HD*HD, mm, cw2 + (size_t)j*HD*HD,
                                         (float*)p_agg4, N);
        k_scatter_bwd<<<scat_blocks, 256>>>(xh, Wth, Wpth, p_agg4, ei, p_gxh4, E);
    }

    // ------- forces -------
    k_force<<<(E + 255) / 256, 256>>>(ei, fout, E);
}

// round 16
// speedup vs baseline: 1.1982x; 1.0229x over previous
#include <cuda_runtime.h>
#include <cuda_fp16.h>
#include <math.h>
#include <stdint.h>

// Problem constants (fixed dataset)
#define NATOMS_MAX 10000
#define NEDGE_MAX  320000
#define HD 128      // hidden = filter dim
#define HD4 (HD/4)
#define GD 50       // gaussians
#define LD 6        // layers

#define NGRID 2048
#define WMAX  6.0f
#define HSTEP (WMAX / (float)(NGRID - 1))
#define INVH  ((float)(NGRID - 1) / WMAX)

#define DELTA   (4.0f/49.0f)
#define COEF    (-0.5f/(DELTA*DELTA))
#define TWOC    (2.0f*COEF)
#define PI_F    3.14159265358979323846f
#define LN2_F   0.6931471805599453f

// ---------------- scratch (static device globals; no allocation) ----------------
__device__ float g_vec[(size_t)NEDGE_MAX*3];
__device__ float g_w[NEDGE_MAX];
__device__ float4 g_epk[NEDGE_MAX];   // packed per-edge: {t, C, dC, bitcast(r)}
__device__ float g_gradw[NEDGE_MAX];

// filter tables: fp32 staging (GEMM out) + fp16 final
__device__ float g_Wt32 [(size_t)LD*NGRID*HD];
__device__ float g_Wpt32[(size_t)LD*NGRID*HD];
__device__ __half g_Wth [(size_t)LD*NGRID*HD];
__device__ __half g_Wpth[(size_t)LD*NGRID*HD];
__device__ float g_eag  [(size_t)NGRID*GD];
__device__ float g_deag [(size_t)NGRID*GD];
__device__ float g_t1g  [(size_t)LD*NGRID*HD];
__device__ float g_dt1g [(size_t)LD*NGRID*HD];

__device__ float  g_h   [(size_t)(LD+1)*NATOMS_MAX*HD];
__device__ __half g_xhh [(size_t)LD*NATOMS_MAX*HD];    // fp16 scatter operand
__device__ float  g_m   [(size_t)LD*NATOMS_MAX*HD];
__device__ float4 g_agg4[(size_t)NATOMS_MAX*HD4];      // fp32 red accumulator
__device__ float  g_gh  [(size_t)NATOMS_MAX*HD];
__device__ float4 g_gxh4[(size_t)NATOMS_MAX*HD4];      // fp32 red accumulator
__device__ __half g_gaggh[(size_t)NATOMS_MAX*HD];      // fp16 scatter operand

// ---------------- math helpers ----------------
__device__ __forceinline__ float sspf(float x) {
    return fmaxf(x, 0.0f) + log1pf(expf(-fabsf(x))) - LN2_F;
}
__device__ __forceinline__ float sigf(float x) {
    return 1.0f / (1.0f + expf(-x));
}
__device__ __forceinline__ void red_add_v4(float* p, float4 v) {
    asm volatile("red.global.add.v4.f32 [%0], {%1,%2,%3,%4};"
                 :: "l"(p), "f"(v.x), "f"(v.y), "f"(v.z), "f"(v.w) : "memory");
}
// load 4 consecutive halves -> float4 (8-byte aligned)
__device__ __forceinline__ float4 ld_half4(const __half* __restrict__ p) {
    uint2 u = *(const uint2*)p;
    float2 a = __half22float2(*(__half2*)&u.x);
    float2 b = __half22float2(*(__half2*)&u.y);
    return make_float4(a.x, a.y, b.x, b.y);
}
// store 8 floats as 8 halves (16-byte aligned)
__device__ __forceinline__ void st_half8(__half* __restrict__ p, const float* v) {
    __half2 h0 = __floats2half2_rn(v[0], v[1]);
    __half2 h1 = __floats2half2_rn(v[2], v[3]);
    __half2 h2 = __floats2half2_rn(v[4], v[5]);
    __half2 h3 = __floats2half2_rn(v[6], v[7]);
    uint4 u;
    u.x = *(uint32_t*)&h0; u.y = *(uint32_t*)&h1;
    u.z = *(uint32_t*)&h2; u.w = *(uint32_t*)&h3;
    *(uint4*)p = u;
}
// lerp a 128-ch fp16 table row pair at (i0, f); lane handles 4 channels
__device__ __forceinline__ float4 lerp_row_h(const __half* __restrict__ tab,
                                             int i0, float f, int lane) {
    const char* base = (const char*)(tab + (size_t)i0 * HD + lane * 4);
    uint2 ua = *(const uint2*)base;
    uint2 ub = *(const uint2*)(base + HD * 2);
    float2 a0 = __half22float2(*(__half2*)&ua.x);
    float2 a1 = __half22float2(*(__half2*)&ua.y);
    float2 b0 = __half22float2(*(__half2*)&ub.x);
    float2 b1 = __half22float2(*(__half2*)&ub.y);
    float4 o;
    o.x = fmaf(f, b0.x - a0.x, a0.x);
    o.y = fmaf(f, b0.y - a0.y, a0.y);
    o.z = fmaf(f, b1.x - a1.x, a1.x);
    o.w = fmaf(f, b1.y - a1.y, a1.y);
    return o;
}

// ---------------- edge geometry (+ packed params) ----------------
__global__ void k_edge_geom(const float* __restrict__ pos, const int* __restrict__ ei,
                            const float* __restrict__ off, const float* __restrict__ cell, int E) {
    int e = blockIdx.x * blockDim.x + threadIdx.x;
    if (e >= E) return;
    int r = ei[e], c = ei[E + e];
    float o0 = off[e*3+0], o1 = off[e*3+1], o2 = off[e*3+2];
    float v0 = pos[r*3+0] - pos[c*3+0] + o0*cell[0] + o1*cell[3] + o2*cell[6];
    float v1 = pos[r*3+1] - pos[c*3+1] + o0*cell[1] + o1*cell[4] + o2*cell[7];
    float v2 = pos[r*3+2] - pos[c*3+2] + o0*cell[2] + o1*cell[5] + o2*cell[8];
    float w = sqrtf(v0*v0 + v1*v1 + v2*v2);
    g_vec[(size_t)e*3+0] = v0; g_vec[(size_t)e*3+1] = v1; g_vec[(size_t)e*3+2] = v2;
    g_w[e] = w;
    float a = w * (PI_F / 4.0f);
    float C  = 0.5f * (cosf(a) + 1.0f);
    float dC = -0.5f * sinf(a) * (PI_F / 4.0f);
    float t  = fminf(w, WMAX) * INVH;
    g_epk[e] = make_float4(t, C, dC, __int_as_float(r));
}

// ---------------- gaussian grid (once) ----------------
__global__ void k_tab_ea() {
    int idx = blockIdx.x * blockDim.x + threadIdx.x;
    if (idx >= NGRID * GD) return;
    int g = idx / GD, j = idx % GD;
    float w = (float)g * HSTEP;
    float d = w - (float)j * DELTA;
    float ea = expf(COEF * d * d);
    g_eag[idx]  = ea;
    g_deag[idx] = TWOC * d * ea;
}

__global__ void k_h0(const int* __restrict__ z, const float* __restrict__ emb,
                     float* __restrict__ h, int N) {
    int idx = blockIdx.x * blockDim.x + threadIdx.x;
    if (idx >= N * HD) return;
    int n = idx >> 7, k = idx & 127;
    h[idx] = emb[(size_t)z[n] * HD + k];
}

__global__ void k_cvt_h(const float* __restrict__ a, const float* __restrict__ b,
                        __half* __restrict__ ha, __half* __restrict__ hb, size_t n) {
    size_t i = (size_t)blockIdx.x * blockDim.x + threadIdx.x;
    if (i >= n) return;
    ha[i] = __float2half_rn(a[i]);
    hb[i] = __float2half_rn(b[i]);
}

// ---------------- tiled fp32 GEMM (tables + xh0); OUTH: store output as fp16 ----------------
template<bool TB, int AOP, int EPI, bool OUTH>
__global__ __launch_bounds__(256)
void k_gemm(const float* __restrict__ A, const float* __restrict__ B,
            const float* __restrict__ bias, const float* __restrict__ add_,
            const float* __restrict__ aux, void* __restrict__ Co_,
            int M, int Nn, int K,
            size_t sA, size_t sB, size_t sBias, size_t sC) {
    const int BM = 64, BN = 64, BK = 16;
    int zb = blockIdx.z;
    A  += (size_t)zb * sA;
    B  += (size_t)zb * sB;
    float*  Cf = OUTH ? nullptr : ((float*)Co_) + (size_t)zb * sC;
    __half* Ch = OUTH ? ((__half*)Co_) + (size_t)zb * sC : nullptr;
    const float* bi = bias ? bias + (size_t)zb * sBias : nullptr;
    const float* ax2 = (AOP == 2) ? add_ + (size_t)zb * sA : nullptr;

    __shared__ float As[BK][BM + 4];
    __shared__ float Bs[BK][BN + 4];
    int bm = blockIdx.y * BM, bn = blockIdx.x * BN;
    int tid = threadIdx.x;
    int tx = tid & 15, ty = tid >> 4;
    int la_k = tid & 15, la_r = tid >> 4;
    float acc[4][4];
#pragma unroll
    for (int i = 0; i < 4; i++)
#pragma unroll
        for (int j = 0; j < 4; j++) acc[i][j] = 0.0f;

    for (int k0 = 0; k0 < K; k0 += BK) {
#pragma unroll
        for (int i = 0; i < 4; i++) {
            int m = bm + la_r + i * 16;
            int k = k0 + la_k;
            float v = 0.0f;
            if (m < M && k < K) {
                v = A[(size_t)m * K + k];
                if (AOP == 1) v = sspf(v);
                if (AOP == 2) v *= sigf(ax2[(size_t)m * K + k]);
            }
            As[la_k][la_r + i * 16] = v;
        }
#pragma unroll
        for (int i = 0; i < 4; i++) {
            int idx = tid + i * 256;
            int kk = idx >> 6;
            int nn = idx & 63;
            int k = k0 + kk, n = bn + nn;
            float v = 0.0f;
            if (k < K && n < Nn) v = TB ? B[(size_t)n * K + k] : B[(size_t)k * Nn + n];
            Bs[kk][nn] = v;
        }
        __syncthreads();
#pragma unroll
        for (int k = 0; k < BK; k++) {
            float ra[4], rb[4];
#pragma unroll
            for (int i = 0; i < 4; i++) ra[i] = As[k][ty * 4 + i];
#pragma unroll
            for (int j = 0; j < 4; j++) rb[j] = Bs[k][tx * 4 + j];
#pragma unroll
            for (int i = 0; i < 4; i++)
#pragma unroll
                for (int j = 0; j < 4; j++) acc[i][j] = fmaf(ra[i], rb[j], acc[i][j]);
        }
        __syncthreads();
    }
#pragma unroll
    for (int i = 0; i < 4; i++) {
        int m = bm + ty * 4 + i;
        if (m >= M) continue;
#pragma unroll
        for (int j = 0; j < 4; j++) {
            int n = bn + tx * 4 + j;
            if (n >= Nn) continue;
            float v = acc[i][j];
            if (bi) v += bi[n];
            size_t o = (size_t)m * Nn + n;
            if (EPI == 1) v += add_[o];
            if (EPI == 2) v *= sigf(aux[o]);
            if (OUTH) Ch[o] = __float2half_rn(v);
            else      Cf[o] = v;
        }
    }
}

// ============ fused multi-stage node kernels (64-row blocks, 256 thr) ============
__device__ __forceinline__ void load_B_nt(const float* __restrict__ B, float Bs[16][132],
                                          int k0, int tid) {
#pragma unroll
    for (int i = 0; i < 8; i++) {
        int idx = tid + i * 256;
        int kk = idx >> 7, nn = idx & 127;
        Bs[kk][nn] = B[(size_t)(k0 + kk) * HD + nn];
    }
}
__device__ __forceinline__ void load_B_t(const float* __restrict__ B, float Bs[16][132],
                                         int k0, int tid) {
#pragma unroll
    for (int i = 0; i < 8; i++) {
        int idx = tid + i * 256;
        int kk = idx & 15, nn = idx >> 4;
        Bs[kk][nn] = B[(size_t)nn * HD + (k0 + kk)];
    }
}
__device__ __forceinline__ void fma_as(const float As[16][68], const float Bs[16][132],
                                       float acc[4][8], int tx, int ty) {
#pragma unroll
    for (int k = 0; k < 16; k++) {
        float4 a  = *(const float4*)&As[k][ty * 4];
        float4 b0 = *(const float4*)&Bs[k][tx * 8];
        float4 b1 = *(const float4*)&Bs[k][tx * 8 + 4];
        float ra[4] = {a.x, a.y, a.z, a.w};
        float rb[8] = {b0.x, b0.y, b0.z, b0.w, b1.x, b1.y, b1.z, b1.w};
#pragma unroll
        for (int i = 0; i < 4; i++)
#pragma unroll
            for (int j = 0; j < 8; j++) acc[i][j] = fmaf(ra[i], rb[j], acc[i][j]);
    }
}
__device__ __forceinline__ void fma_ms(const float Ms[64][132], const float Bs[16][132],
                                       float acc[4][8], int k0, int tx, int ty) {
#pragma unroll
    for (int k = 0; k < 16; k++) {
        float ra[4];
#pragma unroll
        for (int i = 0; i < 4; i++) ra[i] = Ms[ty * 4 + i][k0 + k];
        float4 b0 = *(const float4*)&Bs[k][tx * 8];
        float4 b1 = *(const float4*)&Bs[k][tx * 8 + 4];
        float rb[8] = {b0.x, b0.y, b0.z, b0.w, b1.x, b1.y, b1.z, b1.w};
#pragma unroll
        for (int i = 0; i < 4; i++)
#pragma unroll
            for (int j = 0; j < 8; j++) acc[i][j] = fmaf(ra[i], rb[j], acc[i][j]);
    }
}
__device__ __forceinline__ void load_A_g(const float* __restrict__ A, float As[16][68],
                                         int bm, int k0, int tid, int N) {
#pragma unroll
    for (int i = 0; i < 4; i++) {
        int idx = tid + i * 256;
        int kk = idx & 15, rr = idx >> 4;
        int gm = bm + rr;
        As[kk][rr] = (gm < N) ? A[(size_t)gm * HD + k0 + kk] : 0.0f;
    }
}
__device__ __forceinline__ void zero_acc(float acc[4][8]) {
#pragma unroll
    for (int i = 0; i < 4; i++)
#pragma unroll
        for (int j = 0; j < 8; j++) acc[i][j] = 0.0f;
}

// fused forward per layer: m = agg@w2+b2 ; hn = hi + ssp(m)@lw+lb ; xhn(fp16) = hn@cw1n
// ALSO re-zeros agg rows after consuming.
__global__ __launch_bounds__(256)
void k_fused_fwd(float* __restrict__ agg, const float* __restrict__ w2,
                 const float* __restrict__ b2, const float* __restrict__ lw,
                 const float* __restrict__ lb, const float* __restrict__ hi,
                 const float* __restrict__ cw1n,
                 float* __restrict__ m_out, float* __restrict__ hn,
                 __half* __restrict__ xhn, int N) {
    __shared__ float As[16][68];
    __shared__ float Bs[16][132];
    __shared__ float Ms[64][132];
    int bm = blockIdx.x * 64;
    int tid = threadIdx.x, tx = tid & 15, ty = tid >> 4;
    float acc[4][8];
    zero_acc(acc);

    // stage 1: m = agg @ w2
    for (int k0 = 0; k0 < HD; k0 += 16) {
        load_A_g(agg, As, bm, k0, tid, N);
        load_B_nt(w2, Bs, k0, tid);
        __syncthreads();
        fma_as(As, Bs, acc, tx, ty);
        __syncthreads();
    }
    const float4 z4 = make_float4(0.f, 0.f, 0.f, 0.f);
#pragma unroll
    for (int i = 0; i < 4; i++) {
        int gm = bm + ty * 4 + i;
        float4 v0, v1;
        float* vv0 = (float*)&v0; float* vv1 = (float*)&v1;
#pragma unroll
        for (int j = 0; j < 8; j++) {
            int c = tx * 8 + j;
            float v = acc[i][j] + b2[c];
            Ms[ty * 4 + i][c] = sspf(v);
            if (j < 4) vv0[j] = v; else vv1[j - 4] = v;
            acc[i][j] = 0.0f;
        }
        if (gm < N) {
            *(float4*)&m_out[(size_t)gm * HD + tx * 8]     = v0;
            *(float4*)&m_out[(size_t)gm * HD + tx * 8 + 4] = v1;
            *(float4*)&agg[(size_t)gm * HD + tx * 8]     = z4;
            *(float4*)&agg[(size_t)gm * HD + tx * 8 + 4] = z4;
        }
    }
    __syncthreads();

    // stage 2: hn = Ms(ssp(m)) @ lw + lb + hi
    for (int k0 = 0; k0 < HD; k0 += 16) {
        load_B_nt(lw, Bs, k0, tid);
        __syncthreads();
        fma_ms(Ms, Bs, acc, k0, tx, ty);
        __syncthreads();
    }
#pragma unroll
    for (int i = 0; i < 4; i++) {
        int gm = bm + ty * 4 + i;
        float hiv[8];
        if (gm < N) {
            float4 a = *(const float4*)&hi[(size_t)gm * HD + tx * 8];
            float4 b = *(const float4*)&hi[(size_t)gm * HD + tx * 8 + 4];
            hiv[0]=a.x; hiv[1]=a.y; hiv[2]=a.z; hiv[3]=a.w;
            hiv[4]=b.x; hiv[5]=b.y; hiv[6]=b.z; hiv[7]=b.w;
        } else {
#pragma unroll
            for (int j = 0; j < 8; j++) hiv[j] = 0.0f;
        }
        float4 v0, v1;
        float* vv0 = (float*)&v0; float* vv1 = (float*)&v1;
#pragma unroll
        for (int j = 0; j < 8; j++) {
            int c = tx * 8 + j;
            float v = acc[i][j] + lb[c] + hiv[j];
            Ms[ty * 4 + i][c] = v;    // safe: all stage-2 reads done (last sync)
            if (j < 4) vv0[j] = v; else vv1[j - 4] = v;
            acc[i][j] = 0.0f;
        }
        if (gm < N) {
            *(float4*)&hn[(size_t)gm * HD + tx * 8]     = v0;
            *(float4*)&hn[(size_t)gm * HD + tx * 8 + 4] = v1;
        }
    }
    if (!cw1n) return;
    __syncthreads();

    // stage 3: xhn(fp16) = Ms(hn) @ cw1n
    for (int k0 = 0; k0 < HD; k0 += 16) {
        load_B_nt(cw1n, Bs, k0, tid);
        __syncthreads();
        fma_ms(Ms, Bs, acc, k0, tx, ty);
        __syncthreads();
    }
#pragma unroll
    for (int i = 0; i < 4; i++) {
        int gm = bm + ty * 4 + i;
        if (gm >= N) continue;
        st_half8(xhn + (size_t)gm * HD + tx * 8, acc[i]);
    }
}

// fused backward per layer j; gagg out in fp16; re-zeros gxh rows.
__global__ __launch_bounds__(256)
void k_fused_bwd(float* __restrict__ gh, float* __restrict__ gxh, int has_gxh,
                 const float* __restrict__ cw1n, const float* __restrict__ lw,
                 const float* __restrict__ m, const float* __restrict__ w2,
                 __half* __restrict__ gaggh, int N) {
    __shared__ float As[16][68];
    __shared__ float Bs[16][132];
    __shared__ float Ms[64][132];
    int bm = blockIdx.x * 64;
    int tid = threadIdx.x, tx = tid & 15, ty = tid >> 4;
    float acc[4][8];
    zero_acc(acc);

    // stage 0: gh += gxh @ cw1n^T
    if (has_gxh) {
        for (int k0 = 0; k0 < HD; k0 += 16) {
            load_A_g(gxh, As, bm, k0, tid, N);
            load_B_t(cw1n, Bs, k0, tid);
            __syncthreads();
            fma_as(As, Bs, acc, tx, ty);
            __syncthreads();
        }
    }
    const float4 z4 = make_float4(0.f, 0.f, 0.f, 0.f);
#pragma unroll
    for (int i = 0; i < 4; i++) {
        int gm = bm + ty * 4 + i;
        float ghv[8];
        if (gm < N) {
            float4 a = *(const float4*)&gh[(size_t)gm * HD + tx * 8];
            float4 b = *(const float4*)&gh[(size_t)gm * HD + tx * 8 + 4];
            ghv[0]=a.x; ghv[1]=a.y; ghv[2]=a.z; ghv[3]=a.w;
            ghv[4]=b.x; ghv[5]=b.y; ghv[6]=b.z; ghv[7]=b.w;
        } else {
#pragma unroll
            for (int j = 0; j < 8; j++) ghv[j] = 0.0f;
        }
        float4 v0, v1;
        float* vv0 = (float*)&v0; float* vv1 = (float*)&v1;
#pragma unroll
        for (int j = 0; j < 8; j++) {
            int c = tx * 8 + j;
            float v = acc[i][j] + ghv[j];
            Ms[ty * 4 + i][c] = v;
            if (j < 4) vv0[j] = v; else vv1[j - 4] = v;
            acc[i][j] = 0.0f;
        }
        if (gm < N) {
            if (has_gxh) {
                *(float4*)&gh[(size_t)gm * HD + tx * 8]     = v0;
                *(float4*)&gh[(size_t)gm * HD + tx * 8 + 4] = v1;
            }
            *(float4*)&gxh[(size_t)gm * HD + tx * 8]     = z4;
            *(float4*)&gxh[(size_t)gm * HD + tx * 8 + 4] = z4;
        }
    }
    __syncthreads();

    // stage 1: t = Ms(gh) @ lw^T, gate by sigmoid(m)
    for (int k0 = 0; k0 < HD; k0 += 16) {
        load_B_t(lw, Bs, k0, tid);
        __syncthreads();
        fma_ms(Ms, Bs, acc, k0, tx, ty);
        __syncthreads();
    }
#pragma unroll
    for (int i = 0; i < 4; i++) {
        int gm = bm + ty * 4 + i;
        float mv[8];
        if (gm < N) {
            float4 a = *(const float4*)&m[(size_t)gm * HD + tx * 8];
            float4 b = *(const float4*)&m[(size_t)gm * HD + tx * 8 + 4];
            mv[0]=a.x; mv[1]=a.y; mv[2]=a.z; mv[3]=a.w;
            mv[4]=b.x; mv[5]=b.y; mv[6]=b.z; mv[7]=b.w;
        } else {
#pragma unroll
            for (int j = 0; j < 8; j++) mv[j] = 0.0f;
        }
#pragma unroll
        for (int j = 0; j < 8; j++) {
            int c = tx * 8 + j;
            Ms[ty * 4 + i][c] = acc[i][j] * sigf(mv[j]);
            acc[i][j] = 0.0f;
        }
    }
    __syncthreads();

    // stage 2: gagg(fp16) = Ms(gn) @ w2^T
    for (int k0 = 0; k0 < HD; k0 += 16) {
        load_B_t(w2, Bs, k0, tid);
        __syncthreads();
        fma_ms(Ms, Bs, acc, k0, tx, ty);
        __syncthreads();
    }
#pragma unroll
    for (int i = 0; i < 4; i++) {
        int gm = bm + ty * 4 + i;
        if (gm >= N) continue;
        st_half8(gaggh + (size_t)gm * HD + tx * 8, acc[i]);
    }
}

// ---------------- scatter forward: warp per edge, fp16 operands, red.v4 ----------------
__global__ __launch_bounds__(256)
void k_scatter_fwd(const __half* __restrict__ xh, const __half* __restrict__ Wth,
                   const int* __restrict__ ei, float4* __restrict__ agg, int E) {
    int e = (int)(((size_t)blockIdx.x * blockDim.x + threadIdx.x) >> 5);
    int lane = threadIdx.x & 31;
    if (e >= E) return;
    float4 pk = g_epk[e];
    float t = pk.x, cc = pk.y;
    int r = __float_as_int(pk.w);
    int c = ei[E + e];
    int i0 = min((int)t, NGRID - 2);
    float f = t - (float)i0;
    float4 W = lerp_row_h(Wth, i0, f, lane);
    float4 x = ld_half4(xh + (size_t)r * HD + lane * 4);
    float4 v;
    v.x = W.x * cc * x.x;
    v.y = W.y * cc * x.y;
    v.z = W.z * cc * x.z;
    v.w = W.w * cc * x.w;
    red_add_v4((float*)(agg + (size_t)c * HD4 + lane), v);
}

// ---------------- scatter backward: warp per edge ----------------
__global__ __launch_bounds__(256)
void k_scatter_bwd(const __half* __restrict__ xh, const __half* __restrict__ Wth,
                   const __half* __restrict__ Wpth,
                   const __half* __restrict__ gaggh, const int* __restrict__ ei,
                   float4* __restrict__ gxh, int E) {
    int e = (int)(((size_t)blockIdx.x * blockDim.x + threadIdx.x) >> 5);
    int lane = threadIdx.x & 31;
    if (e >= E) return;
    float4 pk = g_epk[e];
    float t = pk.x, cc = pk.y, dc = pk.z;
    int r = __float_as_int(pk.w);
    int c = ei[E + e];
    int i0 = min((int)t, NGRID - 2);
    float f = t - (float)i0;
    float4 W  = lerp_row_h(Wth,  i0, f, lane);
    float4 Wp = lerp_row_h(Wpth, i0, f, lane);
    float4 x = ld_half4(xh    + (size_t)r * HD + lane * 4);
    float4 g = ld_half4(gaggh + (size_t)c * HD + lane * 4);

    float gws;
    gws  = (x.x * g.x) * fmaf(cc, Wp.x, dc * W.x);
    gws += (x.y * g.y) * fmaf(cc, Wp.y, dc * W.y);
    gws += (x.z * g.z) * fmaf(cc, Wp.z, dc * W.z);
    gws += (x.w * g.w) * fmaf(cc, Wp.w, dc * W.w);
    float4 gx;
    gx.x = W.x * cc * g.x;
    gx.y = W.y * cc * g.y;
    gx.z = W.z * cc * g.z;
    gx.w = W.w * cc * g.w;
    red_add_v4((float*)(gxh + (size_t)r * HD4 + lane), gx);
#pragma unroll
    for (int o = 16; o > 0; o >>= 1) gws += __shfl_xor_sync(0xffffffffu, gws, o);
    if (lane == 0) g_gradw[e] += gws;   // unique writer per edge per pass
}

// ---------------- forces ----------------
__global__ void k_force(const int* __restrict__ ei, float* __restrict__ fout, int E) {
    int e = blockIdx.x * blockDim.x + threadIdx.x;
    if (e >= E) return;
    float w = g_w[e];
    float s = (w > 1e-12f) ? (g_gradw[e] / w) : 0.0f;
    int r = ei[e], c = ei[E + e];
#pragma unroll
    for (int d = 0; d < 3; d++) {
        float f = s * g_vec[(size_t)e * 3 + d];
        atomicAdd(&fout[r * 3 + d], -f);
        atomicAdd(&fout[c * 3 + d],  f);
    }
}

// ---------------- readout as blocked GEMM (64-row blocks): energy + grad_hL ----------------
__global__ __launch_bounds__(256)
void k_readout(const float* __restrict__ hL,
               const float* __restrict__ o1w, const float* __restrict__ o1b,
               const float* __restrict__ o2w, const float* __restrict__ o2b,
               float* __restrict__ gh, float* __restrict__ out_e, int N) {
    __shared__ float As[16][68];
    __shared__ float Bs[16][132];
    __shared__ float Us[64][68];
    __shared__ float yp[16][68];
    __shared__ float ys[64];
    int bm = blockIdx.x * 64;
    int tid = threadIdx.x, tx = tid & 15, ty = tid >> 4;

    // ---- stage 1: u = h @ o1w (64x64, K=128) ----
    float acc[4][4];
#pragma unroll
    for (int i = 0; i < 4; i++)
#pragma unroll
        for (int j = 0; j < 4; j++) acc[i][j] = 0.0f;
    for (int k0 = 0; k0 < HD; k0 += 16) {
        load_A_g(hL, As, bm, k0, tid, N);
#pragma unroll
        for (int i = 0; i < 4; i++) {
            int idx = tid + i * 256;
            int kk = idx >> 6, nn = idx & 63;
            Bs[kk][nn] = o1w[(size_t)(k0 + kk) * 64 + nn];
        }
        __syncthreads();
#pragma unroll
        for (int k = 0; k < 16; k++) {
            float ra[4], rb[4];
#pragma unroll
            for (int i = 0; i < 4; i++) ra[i] = As[k][ty * 4 + i];
#pragma unroll
            for (int j = 0; j < 4; j++) rb[j] = Bs[k][tx * 4 + j];
#pragma unroll
            for (int i = 0; i < 4; i++)
#pragma unroll
                for (int j = 0; j < 4; j++) acc[i][j] = fmaf(ra[i], rb[j], acc[i][j]);
        }
        __syncthreads();
    }
#pragma unroll
    for (int i = 0; i < 4; i++) {
        int row = ty * 4 + i;
        float rs = 0.0f;
#pragma unroll
        for (int j = 0; j < 4; j++) {
            int cidx = tx * 4 + j;
            float u = acc[i][j] + o1b[cidx];
            float w2v = o2w[cidx];
            Us[row][cidx] = w2v * sigf(u);
            rs = fmaf(sspf(u), w2v, rs);
        }
        yp[tx][row] = rs;
    }
    __syncthreads();
    if (tid < 64) {
        float v = 0.0f;
#pragma unroll
        for (int p = 0; p < 16; p++) v += yp[p][tid];
        ys[tid] = (bm + tid < N) ? (v + o2b[0]) : 0.0f;
    }
    __syncthreads();
    if (tid == 0) {
        float s = 0.0f;
        for (int rr = 0; rr < 64; rr++) s += ys[rr];
        atomicAdd(out_e, s);
    }

    // ---- stage 2: gh = Us(Gu) @ o1w^T (64x128, K=64) ----
    float acc2[4][8];
    zero_acc(acc2);
    for (int j0 = 0; j0 < 64; j0 += 16) {
        __syncthreads();
#pragma unroll
        for (int i = 0; i < 8; i++) {
            int idx = tid + i * 256;
            int jj = idx & 15, k = idx >> 4;
            Bs[jj][k] = o1w[(size_t)k * 64 + j0 + jj];
        }
        __syncthreads();
#pragma unroll
        for (int jj = 0; jj < 16; jj++) {
            float ra[4];
#pragma unroll
            for (int i = 0; i < 4; i++) ra[i] = Us[ty * 4 + i][j0 + jj];
            float4 b0 = *(const float4*)&Bs[jj][tx * 8];
            float4 b1 = *(const float4*)&Bs[jj][tx * 8 + 4];
            float rb[8] = {b0.x, b0.y, b0.z, b0.w, b1.x, b1.y, b1.z, b1.w};
#pragma unroll
            for (int i = 0; i < 4; i++)
#pragma unroll
                for (int j = 0; j < 8; j++) acc2[i][j] = fmaf(ra[i], rb[j], acc2[i][j]);
        }
    }
#pragma unroll
    for (int i = 0; i < 4; i++) {
        int gm = bm + ty * 4 + i;
        if (gm >= N) continue;
        float4 v0, v1;
        v0.x=acc2[i][0]; v0.y=acc2[i][1]; v0.z=acc2[i][2]; v0.w=acc2[i][3];
        v1.x=acc2[i][4]; v1.y=acc2[i][5]; v1.z=acc2[i][6]; v1.w=acc2[i][7];
        *(float4*)&gh[(size_t)gm * HD + tx * 8]     = v0;
        *(float4*)&gh[(size_t)gm * HD + tx * 8 + 4] = v1;
    }
}

// ---------------- launch ----------------
extern "C" void kernel_launch(void* const* d_in, const int* in_sizes, int n_in,
                              void* d_out, int out_size) {
    const int*   z    = (const int*)  d_in[0];
    const float* pos  = (const float*)d_in[1];
    const int*   ei   = (const int*)  d_in[2];
    const float* off  = (const float*)d_in[3];
    const float* cell = (const float*)d_in[4];
    const float* emb  = (const float*)d_in[5];
    const float* mw1  = (const float*)d_in[6];
    const float* mb1  = (const float*)d_in[7];
    const float* mw2  = (const float*)d_in[8];
    const float* mb2  = (const float*)d_in[9];
    const float* cw1  = (const float*)d_in[10];
    const float* cw2  = (const float*)d_in[11];
    const float* cb2  = (const float*)d_in[12];
    const float* lw   = (const float*)d_in[13];
    const float* lb   = (const float*)d_in[14];
    const float* o1w  = (const float*)d_in[15];
    const float* o1b  = (const float*)d_in[16];
    const float* o2w  = (const float*)d_in[17];
    const float* o2b  = (const float*)d_in[18];
    int N = in_sizes[0];
    int E = in_sizes[2] / 2;
    float* out = (float*)d_out;
    float* fout = out + 1;

    float4 *p_agg4, *p_gxh4;
    float *p_eag, *p_deag, *p_t1g, *p_dt1g, *p_Wt32, *p_Wpt32;
    __half *p_Wth, *p_Wpth, *p_xhh, *p_gaggh;
    float *p_h, *p_m, *p_gh, *p_gradw;
    cudaGetSymbolAddress((void**)&p_Wt32,   g_Wt32);
    cudaGetSymbolAddress((void**)&p_Wpt32,  g_Wpt32);
    cudaGetSymbolAddress((void**)&p_Wth,    g_Wth);
    cudaGetSymbolAddress((void**)&p_Wpth,   g_Wpth);
    cudaGetSymbolAddress((void**)&p_eag,    g_eag);
    cudaGetSymbolAddress((void**)&p_deag,   g_deag);
    cudaGetSymbolAddress((void**)&p_t1g,    g_t1g);
    cudaGetSymbolAddress((void**)&p_dt1g,   g_dt1g);
    cudaGetSymbolAddress((void**)&p_h,      g_h);
    cudaGetSymbolAddress((void**)&p_xhh,    g_xhh);
    cudaGetSymbolAddress((void**)&p_m,      g_m);
    cudaGetSymbolAddress((void**)&p_agg4,   g_agg4);
    cudaGetSymbolAddress((void**)&p_gh,     g_gh);
    cudaGetSymbolAddress((void**)&p_gxh4,   g_gxh4);
    cudaGetSymbolAddress((void**)&p_gaggh,  g_gaggh);
    cudaGetSymbolAddress((void**)&p_gradw,  g_gradw);

    cudaMemsetAsync(out, 0, (size_t)out_size * sizeof(float), 0);
    cudaMemsetAsync(p_gradw, 0, (size_t)E * sizeof(float), 0);
    cudaMemsetAsync(p_agg4, 0, (size_t)N * HD * sizeof(float), 0);  // once; fused_fwd re-zeros

    k_edge_geom<<<(E + 255) / 256, 256>>>(pos, ei, off, cell, E);
    k_h0<<<(N * HD + 255) / 256, 256>>>(z, emb, p_h, N);
    k_tab_ea<<<(NGRID * GD + 255) / 256, 256>>>();

    const size_t sT = (size_t)NGRID * HD;
    dim3 gridTab(HD / 64, NGRID / 64, LD);
    dim3 gridXh0(HD / 64, (N + 63) / 64, 1);
    int nodeBlocks = (N + 63) / 64;
    int scat_blocks = (int)(((size_t)E * 32 + 255) / 256);

    // ------- build filter tables W(w), W'(w), all layers batched; convert to fp16 -------
    k_gemm<false,0,0,false><<<gridTab, 256>>>(p_eag, mw1, mb1, nullptr, nullptr, p_t1g,
                                              NGRID, HD, GD, 0, (size_t)GD*HD, HD, sT);
    k_gemm<false,0,0,false><<<gridTab, 256>>>(p_deag, mw1, nullptr, nullptr, nullptr, p_dt1g,
                                              NGRID, HD, GD, 0, (size_t)GD*HD, 0, sT);
    k_gemm<false,1,0,false><<<gridTab, 256>>>(p_t1g, mw2, mb2, nullptr, nullptr, p_Wt32,
                                              NGRID, HD, HD, sT, (size_t)HD*HD, HD, sT);
    k_gemm<false,2,0,false><<<gridTab, 256>>>(p_dt1g, mw2, nullptr, p_t1g, nullptr, p_Wpt32,
                                              NGRID, HD, HD, sT, (size_t)HD*HD, 0, sT);
    size_t tabN = (size_t)LD * NGRID * HD;
    k_cvt_h<<<(int)((tabN + 255) / 256), 256>>>(p_Wt32, p_Wpt32, p_Wth, p_Wpth, tabN);

    // ------- forward -------
    // xh_0 (fp16) = h_0 @ cw1_0
    k_gemm<false,0,0,true><<<gridXh0, 256>>>(p_h, cw1, nullptr, nullptr, nullptr, p_xhh,
                                             N, HD, HD, 0, 0, 0, 0);
    for (int i = 0; i < LD; i++) {
        const __half* Wth = p_Wth + (size_t)i * NGRID * HD;
        const __half* xh = p_xhh + (size_t)i * N * HD;
        float* hi = p_h + (size_t)i * N * HD;
        float* hn = p_h + (size_t)(i + 1) * N * HD;
        float* mm = p_m + (size_t)i * N * HD;
        const float* cw1n = (i + 1 < LD) ? cw1 + (size_t)(i + 1) * HD * HD : nullptr;
        __half* xhn = (i + 1 < LD) ? p_xhh + (size_t)(i + 1) * N * HD : nullptr;

        k_scatter_fwd<<<scat_blocks, 256>>>(xh, Wth, ei, p_agg4, E);
        k_fused_fwd<<<nodeBlocks, 256>>>((float*)p_agg4, cw2 + (size_t)i*HD*HD, cb2 + i*HD,
                                         lw + (size_t)i*HD*HD, lb + i*HD, hi, cw1n,
                                         mm, hn, xhn, N);
    }

    // ------- readout (energy + grad_h_L) -------
    k_readout<<<nodeBlocks, 256>>>(p_h + (size_t)LD * N * HD, o1w, o1b, o2w, o2b,
                                   p_gh, out, N);

    // ------- backward -------
    for (int j = LD - 1; j >= 0; j--) {
        const __half* Wth  = p_Wth  + (size_t)j * NGRID * HD;
        const __half* Wpth = p_Wpth + (size_t)j * NGRID * HD;
        const __half* xh = p_xhh + (size_t)j * N * HD;
        float* mm = p_m + (size_t)j * N * HD;
        int has_gxh = (j < LD - 1) ? 1 : 0;
        const float* cw1n = (j < LD - 1) ? cw1 + (size_t)(j + 1) * HD * HD : nullptr;

        k_fused_bwd<<<nodeBlocks, 256>>>(p_gh, (float*)p_gxh4, has_gxh, cw1n,
                                         lw + (size_t)j*HD*HD, mm, cw2 + (size_t)j*HD*HD,
                                         p_gaggh, N);
        k_scatter_bwd<<<scat_blocks, 256>>>(xh, Wth, Wpth, p_gaggh, ei, p_gxh4, E);
    }

    // ------- forces -------
    k_force<<<(E + 255) / 256, 256>>>(ei, fout, E);
}